// round 9
// baseline (speedup 1.0000x reference)
#include <cuda_runtime.h>
#include <cuda_bf16.h>
#include <math.h>
#include <cstdint>

#define NUM_NODES 9
#define HIDDEN    512
#define BATCH     8192
#define M_ROWS    (BATCH * NUM_NODES)   // 73728
#define EPS       1e-8f

// Scratch buffers (device globals; no dynamic alloc allowed).
__device__ float g_scratch[(size_t)M_ROWS * HIDDEN];   // x_proj -> h -> mobius out (tf32-rounded)
__device__ float g_w1[HIDDEN * HIDDEN];                // tf32-rounded to_w
__device__ float g_w2[HIDDEN * HIDDEN];                // tf32-rounded from_w
__device__ float g_yy[NUM_NODES * NUM_NODES];          // ||mw[i][j]||^2

__device__ __forceinline__ uint32_t smem_u32(const void* p) {
    uint32_t a;
    asm("{ .reg .u64 t; cvta.to.shared.u64 t, %1; cvt.u32.u64 %0, t; }" : "=r"(a) : "l"(p));
    return a;
}
__device__ __forceinline__ uint32_t cvt_tf32(float f) {
    uint32_t u;
    asm("cvt.rna.tf32.f32 %0, %1;" : "=r"(u) : "f"(f));
    return u;
}

#define CP_ASYNC16(saddr, gptr) \
    asm volatile("cp.async.cg.shared.global [%0], [%1], 16;" :: "r"(saddr), "l"(gptr) : "memory")
#define CP_COMMIT() asm volatile("cp.async.commit_group;" ::: "memory")
#define CP_WAIT(n)  asm volatile("cp.async.wait_group %0;" :: "n"(n) : "memory")

__device__ __forceinline__ void mma_tf32(float* d, const uint32_t* a, const uint32_t* b) {
    asm volatile(
        "mma.sync.aligned.m16n8k8.row.col.f32.tf32.tf32.f32 "
        "{%0,%1,%2,%3}, {%4,%5,%6,%7}, {%8,%9}, {%0,%1,%2,%3};"
        : "+f"(d[0]), "+f"(d[1]), "+f"(d[2]), "+f"(d[3])
        : "r"(a[0]), "r"(a[1]), "r"(a[2]), "r"(a[3]), "r"(b[0]), "r"(b[1]));
}

// ---------------------------------------------------------------------------
// tf32 round prepass (weights only — tiny)
// ---------------------------------------------------------------------------
__global__ void round_kernel(const float4* __restrict__ in, float4* __restrict__ out, int n4) {
    int i = blockIdx.x * blockDim.x + threadIdx.x;
    int stride = gridDim.x * blockDim.x;
    for (; i < n4; i += stride) {
        float4 v = in[i];
        uint4 u = make_uint4(cvt_tf32(v.x), cvt_tf32(v.y), cvt_tf32(v.z), cvt_tf32(v.w));
        out[i] = *(float4*)&u;
    }
}

// ---------------------------------------------------------------------------
// TF32 mma.sync GEMM with cp.async 3-stage pipeline.  (R8 winner, verbatim)
// ---------------------------------------------------------------------------
#define BM 128
#define BN 256
#define LDS_PITCH 36
#define KCHUNKS (HIDDEN / 32)            // 16
#define A_BUF (BM * LDS_PITCH)           // 4608 floats / stage
#define B_BUF (BN * LDS_PITCH)           // 9216 floats / stage
#define STAGES 3
#define DYN_SMEM_BYTES (STAGES * (A_BUF + B_BUF) * 4)   // 165888 B

template<bool CVT_A>
__global__ __launch_bounds__(256)
void gemm_cp(const float* __restrict__ A,
             const float* __restrict__ W,
             const float* __restrict__ bias,
             float* __restrict__ C)
{
    extern __shared__ __align__(16) float smem[];
    const uint32_t smem_base = smem_u32(smem);
    const uint32_t sA0 = smem_base;
    const uint32_t sB0 = smem_base + STAGES * A_BUF * 4;

    const int tid  = threadIdx.x;
    const int bm   = blockIdx.y * BM;
    const int bn   = blockIdx.x * BN;
    const int lane = tid & 31;
    const int wid  = tid >> 5;
    const int m0w  = (wid & 1) * 64;
    const int n0w  = (wid >> 1) * 64;
    const int g    = lane >> 2;
    const int t    = lane & 3;

    const int r = tid >> 3;               // 0..31
    const int q = tid & 7;                // 0..7

    const float* aG = A + (size_t)(bm + r) * HIDDEN + q * 4;
    const float* bG = W + (size_t)(bn + r) * HIDDEN + q * 4;
    const uint32_t aS = sA0 + (uint32_t)(r * LDS_PITCH + q * 4) * 4;
    const uint32_t bS = sB0 + (uint32_t)(r * LDS_PITCH + q * 4) * 4;

    float acc[4][8][4];
#pragma unroll
    for (int mi = 0; mi < 4; mi++)
#pragma unroll
        for (int ni = 0; ni < 8; ni++)
#pragma unroll
            for (int e = 0; e < 4; e++) acc[mi][ni][e] = 0.f;

#define ISSUE_STAGE(ck, st) do { \
    const float* _ag = aG + (ck) * 32; \
    const float* _bg = bG + (ck) * 32; \
    uint32_t _as = aS + (uint32_t)(st) * (A_BUF * 4); \
    uint32_t _bs = bS + (uint32_t)(st) * (B_BUF * 4); \
    _Pragma("unroll") \
    for (int _i = 0; _i < 4; _i++) \
        CP_ASYNC16(_as + _i * 32 * LDS_PITCH * 4, _ag + (size_t)_i * 32 * HIDDEN); \
    _Pragma("unroll") \
    for (int _i = 0; _i < 8; _i++) \
        CP_ASYNC16(_bs + _i * 32 * LDS_PITCH * 4, _bg + (size_t)_i * 32 * HIDDEN); \
    CP_COMMIT(); \
} while (0)

    ISSUE_STAGE(0, 0);
    ISSUE_STAGE(1, 1);

    uint32_t af[2][4][4], bf[2][8][2];

#define LDA(v) (CVT_A ? cvt_tf32(v) : __float_as_uint(v))

    int st = 0;
    for (int ck = 0; ck < KCHUNKS; ck++) {
        if (ck < KCHUNKS - 1) { CP_WAIT(1); } else { CP_WAIT(0); }
        __syncthreads();
        if (ck + 2 < KCHUNKS) {
            int nst = st + 2; if (nst >= STAGES) nst -= STAGES;
            ISSUE_STAGE(ck + 2, nst);
        }

        const float* cA = smem + st * A_BUF;
        const float* cB = smem + STAGES * A_BUF + st * B_BUF;

#pragma unroll
        for (int mi = 0; mi < 4; mi++) {
            const float* ap = cA + (m0w + mi * 16 + g) * LDS_PITCH + t;
            af[0][mi][0] = LDA(ap[0]);
            af[0][mi][1] = LDA(ap[8 * LDS_PITCH]);
            af[0][mi][2] = LDA(ap[4]);
            af[0][mi][3] = LDA(ap[8 * LDS_PITCH + 4]);
        }
#pragma unroll
        for (int ni = 0; ni < 8; ni++) {
            const float* bp = cB + (n0w + ni * 8 + g) * LDS_PITCH + t;
            bf[0][ni][0] = __float_as_uint(bp[0]);
            bf[0][ni][1] = __float_as_uint(bp[4]);
        }

#pragma unroll
        for (int s = 0; s < 4; s++) {
            const int cur = s & 1;
            if (s < 3) {
                const int nxt = cur ^ 1;
                const int kc = (s + 1) * 8;
#pragma unroll
                for (int mi = 0; mi < 4; mi++) {
                    const float* ap = cA + (m0w + mi * 16 + g) * LDS_PITCH + kc + t;
                    af[nxt][mi][0] = LDA(ap[0]);
                    af[nxt][mi][1] = LDA(ap[8 * LDS_PITCH]);
                    af[nxt][mi][2] = LDA(ap[4]);
                    af[nxt][mi][3] = LDA(ap[8 * LDS_PITCH + 4]);
                }
#pragma unroll
                for (int ni = 0; ni < 8; ni++) {
                    const float* bp = cB + (n0w + ni * 8 + g) * LDS_PITCH + kc + t;
                    bf[nxt][ni][0] = __float_as_uint(bp[0]);
                    bf[nxt][ni][1] = __float_as_uint(bp[4]);
                }
            }
#pragma unroll
            for (int mi = 0; mi < 4; mi++)
#pragma unroll
                for (int ni = 0; ni < 8; ni++)
                    mma_tf32(acc[mi][ni], af[cur][mi], bf[cur][ni]);
        }

        st++; if (st >= STAGES) st -= STAGES;
    }
#undef LDA

#pragma unroll
    for (int ni = 0; ni < 8; ni++) {
        const int n = bn + n0w + ni * 8 + t * 2;
        const float b0 = __ldg(&bias[n]);
        const float b1 = __ldg(&bias[n + 1]);
#pragma unroll
        for (int mi = 0; mi < 4; mi++) {
            const int m = bm + m0w + mi * 16 + g;
            float2 v0 = make_float2(acc[mi][ni][0] + b0, acc[mi][ni][1] + b1);
            float2 v1 = make_float2(acc[mi][ni][2] + b0, acc[mi][ni][3] + b1);
            *(float2*)&C[(size_t)m * HIDDEN + n]       = v0;
            *(float2*)&C[(size_t)(m + 8) * HIDDEN + n] = v1;
        }
    }
}

// ---------------------------------------------------------------------------
// warp reductions
// ---------------------------------------------------------------------------
__device__ __forceinline__ float warpSum(float v) {
    v += __shfl_xor_sync(0xffffffffu, v, 16);
    v += __shfl_xor_sync(0xffffffffu, v, 8);
    v += __shfl_xor_sync(0xffffffffu, v, 4);
    v += __shfl_xor_sync(0xffffffffu, v, 2);
    v += __shfl_xor_sync(0xffffffffu, v, 1);
    return v;
}
__device__ __forceinline__ void warpSum2(float& a, float& b) {
#pragma unroll
    for (int m = 16; m >= 1; m >>= 1) {
        a += __shfl_xor_sync(0xffffffffu, a, m);
        b += __shfl_xor_sync(0xffffffffu, b, m);
    }
}

__global__ void yy_kernel(const float* __restrict__ mw) {
    const int idx  = blockIdx.x;
    const int lane = threadIdx.x;
    const float* p = mw + (size_t)idx * HIDDEN;
    float s = 0.f;
#pragma unroll
    for (int u = 0; u < 16; u++) { float v = p[u * 32 + lane]; s += v * v; }
    s = warpSum(s);
    if (lane == 0) g_yy[idx] = s;
}

// ---------------------------------------------------------------------------
// Mobius aggregation: NB=2 batches per block, 9 warps (one node each, 2
// independent chains per warp, interleaved reductions). Register-lean:
// t recomputed in the update loop (bitwise-identical), h_j read from smem.
// ---------------------------------------------------------------------------
#define NB 2
#define MOB_SMEM_BYTES (NB * NUM_NODES * HIDDEN * 4)   // 36864 B

__device__ const int d_ncnt[9]   = {3, 3, 2, 3, 3, 2, 3, 3, 8};
__device__ const int d_nbr[9][8] = {
    {4, 7, 8, 0, 0, 0, 0, 0},
    {0, 6, 8, 0, 0, 0, 0, 0},
    {5, 8, 0, 0, 0, 0, 0, 0},
    {1, 4, 8, 0, 0, 0, 0, 0},
    {6, 3, 8, 0, 0, 0, 0, 0},
    {2, 8, 0, 0, 0, 0, 0, 0},
    {7, 1, 8, 0, 0, 0, 0, 0},
    {3, 0, 8, 0, 0, 0, 0, 0},
    {0, 1, 2, 3, 4, 5, 6, 7}
};

__global__ __launch_bounds__(288, 2)
void mobius_kernel(float* __restrict__ buf,
                   const float* __restrict__ mw,
                   const float* __restrict__ curv)
{
    extern __shared__ __align__(16) float sh[];     // [NB][9][512]
    __shared__ float sh_xx[NB][NUM_NODES];

    const int b0  = blockIdx.x * NB;
    const int tid = threadIdx.x;
    const float c = fabsf(curv[0]);
    float* base = buf + (size_t)b0 * NUM_NODES * HIDDEN;

    for (int idx = tid; idx < NB * NUM_NODES * HIDDEN / 4; idx += 288)
        ((float4*)sh)[idx] = ((const float4*)base)[idx];
    __syncthreads();

    const int w    = tid >> 5;
    const int lane = tid & 31;

    float r[NB][16];
    float rr[NB];
    {
        float n2[NB];
#pragma unroll
        for (int b = 0; b < NB; b++) {
            n2[b] = 0.f;
            const float* hp = sh + (b * NUM_NODES + w) * HIDDEN;
#pragma unroll
            for (int u = 0; u < 16; u++) {
                r[b][u] = hp[u * 32 + lane];
                n2[b] += r[b][u] * r[b][u];
            }
        }
        warpSum2(n2[0], n2[1]);
#pragma unroll
        for (int b = 0; b < NB; b++) {
            float norm  = sqrtf(n2[b]);
            float scale = tanhf(norm) / (norm + EPS);
            rr[b] = scale * scale * n2[b];
            float* hp = sh + (b * NUM_NODES + w) * HIDDEN;
#pragma unroll
            for (int u = 0; u < 16; u++) {
                r[b][u] *= scale;
                hp[u * 32 + lane] = r[b][u];
            }
            if (lane == 0) sh_xx[b][w] = rr[b];
        }
    }
    __syncthreads();

    const int cnt = d_ncnt[w];
    for (int q = 0; q < cnt; q++) {
        const int j = d_nbr[w][q];
        const float* mwp = mw + ((size_t)w * NUM_NODES + j) * HIDDEN;
        const float yy = __ldg(&g_yy[w * NUM_NODES + j]);

        float mv[16];
#pragma unroll
        for (int u = 0; u < 16; u++) mv[u] = __ldg(&mwp[u * 32 + lane]);

        // xy[b] = <h_j(b), mw>
        float xy[NB];
#pragma unroll
        for (int b = 0; b < NB; b++) {
            const float* hp = sh + (b * NUM_NODES + j) * HIDDEN;
            float s = 0.f;
#pragma unroll
            for (int u = 0; u < 16; u++) s += hp[u * 32 + lane] * mv[u];
            xy[b] = s;
        }
        warpSum2(xy[0], xy[1]);

        // t coefficients + rt[b] = <r, t>  (t not stored)
        float ca[NB], cb[NB], inv[NB], tt[NB], rt[NB];
#pragma unroll
        for (int b = 0; b < NB; b++) {
            const float xxj = sh_xx[b][j];
            ca[b]  = 1.f + 2.f * c * xy[b] + c * yy;
            cb[b]  = 1.f - c * xxj;
            inv[b] = 1.f / (1.f + 2.f * c * xy[b] + c * c * xxj * yy + EPS);
            tt[b]  = inv[b] * inv[b] * (ca[b] * ca[b] * xxj + 2.f * ca[b] * cb[b] * xy[b] + cb[b] * cb[b] * yy);
            const float* hp = sh + (b * NUM_NODES + j) * HIDDEN;
            float s = 0.f;
#pragma unroll
            for (int u = 0; u < 16; u++)
                s += r[b][u] * ((ca[b] * hp[u * 32 + lane] + cb[b] * mv[u]) * inv[b]);
            rt[b] = s;
        }
        warpSum2(rt[0], rt[1]);

        // r = mobius_add(r, t, c)  (t recomputed)
#pragma unroll
        for (int b = 0; b < NB; b++) {
            const float ca2  = 1.f + 2.f * c * rt[b] + c * tt[b];
            const float cb2  = 1.f - c * rr[b];
            const float inv2 = 1.f / (1.f + 2.f * c * rt[b] + c * c * rr[b] * tt[b] + EPS);
            const float* hp = sh + (b * NUM_NODES + j) * HIDDEN;
#pragma unroll
            for (int u = 0; u < 16; u++) {
                float tv = (ca[b] * hp[u * 32 + lane] + cb[b] * mv[u]) * inv[b];
                r[b][u] = (ca2 * r[b][u] + cb2 * tv) * inv2;
            }
            rr[b] = inv2 * inv2 * (ca2 * ca2 * rr[b] + 2.f * ca2 * cb2 * rt[b] + cb2 * cb2 * tt[b]);
        }
    }

    // store tf32-rounded (GEMM2 consumes without further conversion)
#pragma unroll
    for (int b = 0; b < NB; b++) {
        float* dst = base + ((size_t)b * NUM_NODES + w) * HIDDEN;
#pragma unroll
        for (int u = 0; u < 16; u++)
            dst[u * 32 + lane] = __uint_as_float(cvt_tf32(r[b][u]));
    }
}

// ---------------------------------------------------------------------------
// kernel_launch
// ---------------------------------------------------------------------------
extern "C" void kernel_launch(void* const* d_in, const int* in_sizes, int n_in,
                              void* d_out, int out_size)
{
    const float* nf     = (const float*)d_in[0];
    const float* curv   = (const float*)d_in[1];
    const float* to_w   = (const float*)d_in[2];
    const float* to_b   = (const float*)d_in[3];
    const float* from_w = (const float*)d_in[4];
    const float* from_b = (const float*)d_in[5];
    const float* mw     = (const float*)d_in[6];
    float* out = (float*)d_out;

    float *scratch, *w1, *w2;
    cudaGetSymbolAddress((void**)&scratch, g_scratch);
    cudaGetSymbolAddress((void**)&w1,      g_w1);
    cudaGetSymbolAddress((void**)&w2,      g_w2);

    cudaFuncSetAttribute(gemm_cp<true>,  cudaFuncAttributeMaxDynamicSharedMemorySize,
                         DYN_SMEM_BYTES);
    cudaFuncSetAttribute(gemm_cp<false>, cudaFuncAttributeMaxDynamicSharedMemorySize,
                         DYN_SMEM_BYTES);
    cudaFuncSetAttribute(mobius_kernel, cudaFuncAttributeMaxDynamicSharedMemorySize,
                         MOB_SMEM_BYTES);

    dim3 gg(HIDDEN / BN, M_ROWS / BM);   // (2, 576)

    // weight prepasses (tiny)
    round_kernel<<<128, 256>>>((const float4*)to_w,   (float4*)w1, HIDDEN * HIDDEN / 4);
    round_kernel<<<128, 256>>>((const float4*)from_w, (float4*)w2, HIDDEN * HIDDEN / 4);
    yy_kernel<<<NUM_NODES * NUM_NODES, 32>>>(mw);

    // 1) x_proj = nf @ to_w.T + to_b  -> scratch  (A rounded in-kernel)
    gemm_cp<true><<<gg, 256, DYN_SMEM_BYTES>>>(nf, w1, to_b, scratch);

    // 2) tanh-normalize + mobius chains, in place (writes tf32-rounded)
    mobius_kernel<<<BATCH / NB, 288, MOB_SMEM_BYTES>>>(scratch, mw, curv);

    // 3) out = r @ from_w.T + from_b  (all inputs pre-rounded)
    gemm_cp<false><<<gg, 256, DYN_SMEM_BYTES>>>(scratch, w2, from_b, out);
}

// round 10
// speedup vs baseline: 1.0941x; 1.0941x over previous
#include <cuda_runtime.h>
#include <cuda_bf16.h>
#include <math.h>
#include <cstdint>

#define NUM_NODES 9
#define HIDDEN    512
#define BATCH     8192
#define M_ROWS    (BATCH * NUM_NODES)   // 73728
#define EPS       1e-8f

// Scratch buffers (device globals; no dynamic alloc allowed).
__device__ float g_scratch[(size_t)M_ROWS * HIDDEN];   // x_proj -> h -> mobius out (tf32-rounded)
__device__ float g_w1[HIDDEN * HIDDEN];                // tf32-rounded to_w
__device__ float g_w2[HIDDEN * HIDDEN];                // tf32-rounded from_w
__device__ float g_yy[NUM_NODES * NUM_NODES];          // ||mw[i][j]||^2

__device__ __forceinline__ uint32_t smem_u32(const void* p) {
    uint32_t a;
    asm("{ .reg .u64 t; cvta.to.shared.u64 t, %1; cvt.u32.u64 %0, t; }" : "=r"(a) : "l"(p));
    return a;
}
__device__ __forceinline__ uint32_t cvt_tf32(float f) {
    uint32_t u;
    asm("cvt.rna.tf32.f32 %0, %1;" : "=r"(u) : "f"(f));
    return u;
}

#define CP_ASYNC16(saddr, gptr) \
    asm volatile("cp.async.cg.shared.global [%0], [%1], 16;" :: "r"(saddr), "l"(gptr) : "memory")
#define CP_COMMIT() asm volatile("cp.async.commit_group;" ::: "memory")
#define CP_WAIT(n)  asm volatile("cp.async.wait_group %0;" :: "n"(n) : "memory")

__device__ __forceinline__ void mma_tf32(float* d, const uint32_t* a, const uint32_t* b) {
    asm volatile(
        "mma.sync.aligned.m16n8k8.row.col.f32.tf32.tf32.f32 "
        "{%0,%1,%2,%3}, {%4,%5,%6,%7}, {%8,%9}, {%0,%1,%2,%3};"
        : "+f"(d[0]), "+f"(d[1]), "+f"(d[2]), "+f"(d[3])
        : "r"(a[0]), "r"(a[1]), "r"(a[2]), "r"(a[3]), "r"(b[0]), "r"(b[1]));
}

// ---------------------------------------------------------------------------
// tf32 round prepass (weights only — tiny)
// ---------------------------------------------------------------------------
__global__ void round_kernel(const float4* __restrict__ in, float4* __restrict__ out, int n4) {
    int i = blockIdx.x * blockDim.x + threadIdx.x;
    int stride = gridDim.x * blockDim.x;
    for (; i < n4; i += stride) {
        float4 v = in[i];
        uint4 u = make_uint4(cvt_tf32(v.x), cvt_tf32(v.y), cvt_tf32(v.z), cvt_tf32(v.w));
        out[i] = *(float4*)&u;
    }
}

// ---------------------------------------------------------------------------
// TF32 mma.sync GEMM, cp.async 3-stage pipeline.
// CTA 128x128, 128 threads, 4 warps (2M x 2N), warp tile 64x64.
// 110.6 KB smem + ~22K regs per CTA -> 2 CTAs/SM (16 warps/SM).
// CVT_A: round A fragments to tf32 at LDS time (A raw f32 in gmem).
// ---------------------------------------------------------------------------
#define BM 128
#define BN 128
#define LDS_PITCH 36
#define KCHUNKS (HIDDEN / 32)            // 16
#define T_BUF (128 * LDS_PITCH)          // 4608 floats / operand / stage
#define STAGES 3
#define DYN_SMEM_BYTES (STAGES * 2 * T_BUF * 4)   // 110592 B

template<bool CVT_A>
__global__ __launch_bounds__(128, 2)
void gemm_cp(const float* __restrict__ A,
             const float* __restrict__ W,
             const float* __restrict__ bias,
             float* __restrict__ C)
{
    extern __shared__ __align__(16) float smem[];
    const uint32_t smem_base = smem_u32(smem);
    const uint32_t sA0 = smem_base;
    const uint32_t sB0 = smem_base + STAGES * T_BUF * 4;

    const int tid  = threadIdx.x;
    const int bm   = blockIdx.y * BM;
    const int bn   = blockIdx.x * BN;
    const int lane = tid & 31;
    const int wid  = tid >> 5;
    const int m0w  = (wid & 1) * 64;
    const int n0w  = (wid >> 1) * 64;
    const int g    = lane >> 2;
    const int t    = lane & 3;

    const int r = tid >> 3;               // 0..15 (rows r + 16*i)
    const int q = tid & 7;                // 0..7

    const float* aG = A + (size_t)(bm + r) * HIDDEN + q * 4;
    const float* bG = W + (size_t)(bn + r) * HIDDEN + q * 4;
    const uint32_t aS = sA0 + (uint32_t)(r * LDS_PITCH + q * 4) * 4;
    const uint32_t bS = sB0 + (uint32_t)(r * LDS_PITCH + q * 4) * 4;

    float acc[4][8][4];
#pragma unroll
    for (int mi = 0; mi < 4; mi++)
#pragma unroll
        for (int ni = 0; ni < 8; ni++)
#pragma unroll
            for (int e = 0; e < 4; e++) acc[mi][ni][e] = 0.f;

#define ISSUE_STAGE(ck, st) do { \
    const float* _ag = aG + (ck) * 32; \
    const float* _bg = bG + (ck) * 32; \
    uint32_t _as = aS + (uint32_t)(st) * (T_BUF * 4); \
    uint32_t _bs = bS + (uint32_t)(st) * (T_BUF * 4); \
    _Pragma("unroll") \
    for (int _i = 0; _i < 8; _i++) \
        CP_ASYNC16(_as + _i * 16 * LDS_PITCH * 4, _ag + (size_t)_i * 16 * HIDDEN); \
    _Pragma("unroll") \
    for (int _i = 0; _i < 8; _i++) \
        CP_ASYNC16(_bs + _i * 16 * LDS_PITCH * 4, _bg + (size_t)_i * 16 * HIDDEN); \
    CP_COMMIT(); \
} while (0)

    ISSUE_STAGE(0, 0);
    ISSUE_STAGE(1, 1);

    uint32_t af[2][4][4], bf[2][8][2];

#define LDA(v) (CVT_A ? cvt_tf32(v) : __float_as_uint(v))

    int st = 0;
    for (int ck = 0; ck < KCHUNKS; ck++) {
        if (ck < KCHUNKS - 1) { CP_WAIT(1); } else { CP_WAIT(0); }
        __syncthreads();
        if (ck + 2 < KCHUNKS) {
            int nst = st + 2; if (nst >= STAGES) nst -= STAGES;
            ISSUE_STAGE(ck + 2, nst);
        }

        const float* cA = smem + st * T_BUF;
        const float* cB = smem + STAGES * T_BUF + st * T_BUF;

#pragma unroll
        for (int mi = 0; mi < 4; mi++) {
            const float* ap = cA + (m0w + mi * 16 + g) * LDS_PITCH + t;
            af[0][mi][0] = LDA(ap[0]);
            af[0][mi][1] = LDA(ap[8 * LDS_PITCH]);
            af[0][mi][2] = LDA(ap[4]);
            af[0][mi][3] = LDA(ap[8 * LDS_PITCH + 4]);
        }
#pragma unroll
        for (int ni = 0; ni < 8; ni++) {
            const float* bp = cB + (n0w + ni * 8 + g) * LDS_PITCH + t;
            bf[0][ni][0] = __float_as_uint(bp[0]);
            bf[0][ni][1] = __float_as_uint(bp[4]);
        }

#pragma unroll
        for (int s = 0; s < 4; s++) {
            const int cur = s & 1;
            if (s < 3) {
                const int nxt = cur ^ 1;
                const int kc = (s + 1) * 8;
#pragma unroll
                for (int mi = 0; mi < 4; mi++) {
                    const float* ap = cA + (m0w + mi * 16 + g) * LDS_PITCH + kc + t;
                    af[nxt][mi][0] = LDA(ap[0]);
                    af[nxt][mi][1] = LDA(ap[8 * LDS_PITCH]);
                    af[nxt][mi][2] = LDA(ap[4]);
                    af[nxt][mi][3] = LDA(ap[8 * LDS_PITCH + 4]);
                }
#pragma unroll
                for (int ni = 0; ni < 8; ni++) {
                    const float* bp = cB + (n0w + ni * 8 + g) * LDS_PITCH + kc + t;
                    bf[nxt][ni][0] = __float_as_uint(bp[0]);
                    bf[nxt][ni][1] = __float_as_uint(bp[4]);
                }
            }
#pragma unroll
            for (int mi = 0; mi < 4; mi++)
#pragma unroll
                for (int ni = 0; ni < 8; ni++)
                    mma_tf32(acc[mi][ni], af[cur][mi], bf[cur][ni]);
        }

        st++; if (st >= STAGES) st -= STAGES;
    }
#undef LDA

    // epilogue: bias + store
#pragma unroll
    for (int ni = 0; ni < 8; ni++) {
        const int n = bn + n0w + ni * 8 + t * 2;
        const float b0 = __ldg(&bias[n]);
        const float b1 = __ldg(&bias[n + 1]);
#pragma unroll
        for (int mi = 0; mi < 4; mi++) {
            const int m = bm + m0w + mi * 16 + g;
            float2 v0 = make_float2(acc[mi][ni][0] + b0, acc[mi][ni][1] + b1);
            float2 v1 = make_float2(acc[mi][ni][2] + b0, acc[mi][ni][3] + b1);
            *(float2*)&C[(size_t)m * HIDDEN + n]       = v0;
            *(float2*)&C[(size_t)(m + 8) * HIDDEN + n] = v1;
        }
    }
}

// ---------------------------------------------------------------------------
// warp reduction + yy precompute
// ---------------------------------------------------------------------------
__device__ __forceinline__ float warpSum(float v) {
    v += __shfl_xor_sync(0xffffffffu, v, 16);
    v += __shfl_xor_sync(0xffffffffu, v, 8);
    v += __shfl_xor_sync(0xffffffffu, v, 4);
    v += __shfl_xor_sync(0xffffffffu, v, 2);
    v += __shfl_xor_sync(0xffffffffu, v, 1);
    return v;
}

__global__ void yy_kernel(const float* __restrict__ mw) {
    const int idx  = blockIdx.x;
    const int lane = threadIdx.x;
    const float* p = mw + (size_t)idx * HIDDEN;
    float s = 0.f;
#pragma unroll
    for (int u = 0; u < 16; u++) { float v = p[u * 32 + lane]; s += v * v; }
    s = warpSum(s);
    if (lane == 0) g_yy[idx] = s;
}

// ---------------------------------------------------------------------------
// Mobius aggregation (R8 NB=1 winner, verbatim): one block per batch
// element, 9 warps (one per node). Writes tf32-rounded output.
// ---------------------------------------------------------------------------
__device__ const int d_ncnt[9]   = {3, 3, 2, 3, 3, 2, 3, 3, 8};
__device__ const int d_nbr[9][8] = {
    {4, 7, 8, 0, 0, 0, 0, 0},
    {0, 6, 8, 0, 0, 0, 0, 0},
    {5, 8, 0, 0, 0, 0, 0, 0},
    {1, 4, 8, 0, 0, 0, 0, 0},
    {6, 3, 8, 0, 0, 0, 0, 0},
    {2, 8, 0, 0, 0, 0, 0, 0},
    {7, 1, 8, 0, 0, 0, 0, 0},
    {3, 0, 8, 0, 0, 0, 0, 0},
    {0, 1, 2, 3, 4, 5, 6, 7}
};

__global__ __launch_bounds__(288)
void mobius_kernel(float* __restrict__ buf,
                   const float* __restrict__ mw,
                   const float* __restrict__ curv)
{
    __shared__ __align__(16) float sh[NUM_NODES * HIDDEN];
    __shared__ float sh_xx[NUM_NODES];

    const int b   = blockIdx.x;
    const int tid = threadIdx.x;
    const float c = fabsf(curv[0]);
    float* base = buf + (size_t)b * NUM_NODES * HIDDEN;

    for (int idx = tid; idx < NUM_NODES * HIDDEN / 4; idx += 288)
        ((float4*)sh)[idx] = ((const float4*)base)[idx];
    __syncthreads();

    const int w    = tid >> 5;
    const int lane = tid & 31;

    float r[16];
    float n2 = 0.f;
#pragma unroll
    for (int u = 0; u < 16; u++) {
        r[u] = sh[w * HIDDEN + u * 32 + lane];
        n2 += r[u] * r[u];
    }
    n2 = warpSum(n2);
    float norm  = sqrtf(n2);
    float scale = tanhf(norm) / (norm + EPS);
    float rr = scale * scale * n2;
#pragma unroll
    for (int u = 0; u < 16; u++) {
        r[u] *= scale;
        sh[w * HIDDEN + u * 32 + lane] = r[u];
    }
    if (lane == 0) sh_xx[w] = rr;
    __syncthreads();

    const int cnt = d_ncnt[w];
    for (int q = 0; q < cnt; q++) {
        const int j = d_nbr[w][q];
        const float* mwp = mw + ((size_t)w * NUM_NODES + j) * HIDDEN;
        const float yy = __ldg(&g_yy[w * NUM_NODES + j]);

        float hj[16], mv[16];
        float xy = 0.f;
#pragma unroll
        for (int u = 0; u < 16; u++) {
            hj[u] = sh[j * HIDDEN + u * 32 + lane];
            mv[u] = __ldg(&mwp[u * 32 + lane]);
            xy += hj[u] * mv[u];
        }
        xy = warpSum(xy);
        const float xxj = sh_xx[j];

        const float ca  = 1.f + 2.f * c * xy + c * yy;
        const float cb  = 1.f - c * xxj;
        const float inv = 1.f / (1.f + 2.f * c * xy + c * c * xxj * yy + EPS);
        const float tt  = inv * inv * (ca * ca * xxj + 2.f * ca * cb * xy + cb * cb * yy);

        float t[16];
        float rt = 0.f;
#pragma unroll
        for (int u = 0; u < 16; u++) {
            t[u] = (ca * hj[u] + cb * mv[u]) * inv;
            rt += r[u] * t[u];
        }
        rt = warpSum(rt);

        const float ca2  = 1.f + 2.f * c * rt + c * tt;
        const float cb2  = 1.f - c * rr;
        const float inv2 = 1.f / (1.f + 2.f * c * rt + c * c * rr * tt + EPS);
#pragma unroll
        for (int u = 0; u < 16; u++)
            r[u] = (ca2 * r[u] + cb2 * t[u]) * inv2;
        rr = inv2 * inv2 * (ca2 * ca2 * rr + 2.f * ca2 * cb2 * rt + cb2 * cb2 * tt);
    }

    // store tf32-rounded (GEMM2 consumes without further conversion)
    float* dst = base + (size_t)w * HIDDEN;
#pragma unroll
    for (int u = 0; u < 16; u++)
        dst[u * 32 + lane] = __uint_as_float(cvt_tf32(r[u]));
}

// ---------------------------------------------------------------------------
// kernel_launch
// ---------------------------------------------------------------------------
extern "C" void kernel_launch(void* const* d_in, const int* in_sizes, int n_in,
                              void* d_out, int out_size)
{
    const float* nf     = (const float*)d_in[0];
    const float* curv   = (const float*)d_in[1];
    const float* to_w   = (const float*)d_in[2];
    const float* to_b   = (const float*)d_in[3];
    const float* from_w = (const float*)d_in[4];
    const float* from_b = (const float*)d_in[5];
    const float* mw     = (const float*)d_in[6];
    float* out = (float*)d_out;

    float *scratch, *w1, *w2;
    cudaGetSymbolAddress((void**)&scratch, g_scratch);
    cudaGetSymbolAddress((void**)&w1,      g_w1);
    cudaGetSymbolAddress((void**)&w2,      g_w2);

    cudaFuncSetAttribute(gemm_cp<true>,  cudaFuncAttributeMaxDynamicSharedMemorySize,
                         DYN_SMEM_BYTES);
    cudaFuncSetAttribute(gemm_cp<false>, cudaFuncAttributeMaxDynamicSharedMemorySize,
                         DYN_SMEM_BYTES);

    dim3 gg(HIDDEN / BN, M_ROWS / BM);   // (4, 576)

    // weight prepasses (tiny)
    round_kernel<<<128, 256>>>((const float4*)to_w,   (float4*)w1, HIDDEN * HIDDEN / 4);
    round_kernel<<<128, 256>>>((const float4*)from_w, (float4*)w2, HIDDEN * HIDDEN / 4);
    yy_kernel<<<NUM_NODES * NUM_NODES, 32>>>(mw);

    // 1) x_proj = nf @ to_w.T + to_b  -> scratch  (A rounded in-kernel)
    gemm_cp<true><<<gg, 128, DYN_SMEM_BYTES>>>(nf, w1, to_b, scratch);

    // 2) tanh-normalize + mobius chains, in place (writes tf32-rounded)
    mobius_kernel<<<BATCH, 288>>>(scratch, mw, curv);

    // 3) out = r @ from_w.T + from_b  (all inputs pre-rounded)
    gemm_cp<false><<<gg, 128, DYN_SMEM_BYTES>>>(scratch, w2, from_b, out);
}

// round 11
// speedup vs baseline: 1.1241x; 1.0274x over previous
#include <cuda_runtime.h>
#include <cuda_bf16.h>
#include <math.h>
#include <cstdint>

#define NUM_NODES 9
#define HIDDEN    512
#define BATCH     8192
#define M_ROWS    (BATCH * NUM_NODES)   // 73728
#define EPS       1e-8f

#define NCHUNKS         4
#define BATCH_PER_CHUNK (BATCH / NCHUNKS)          // 2048
#define ROWS_PER_CHUNK  (BATCH_PER_CHUNK * NUM_NODES)  // 18432 = 144 * 128

// Scratch buffers (device globals; no dynamic alloc allowed).
__device__ float g_scratch[(size_t)M_ROWS * HIDDEN];   // x_proj -> h -> mobius out (tf32-rounded)
__device__ float g_w1[HIDDEN * HIDDEN];                // tf32-rounded to_w
__device__ float g_w2[HIDDEN * HIDDEN];                // tf32-rounded from_w
__device__ float g_yy[NUM_NODES * NUM_NODES];          // ||mw[i][j]||^2

__device__ __forceinline__ uint32_t smem_u32(const void* p) {
    uint32_t a;
    asm("{ .reg .u64 t; cvta.to.shared.u64 t, %1; cvt.u32.u64 %0, t; }" : "=r"(a) : "l"(p));
    return a;
}
__device__ __forceinline__ uint32_t cvt_tf32(float f) {
    uint32_t u;
    asm("cvt.rna.tf32.f32 %0, %1;" : "=r"(u) : "f"(f));
    return u;
}

#define CP_ASYNC16(saddr, gptr) \
    asm volatile("cp.async.cg.shared.global [%0], [%1], 16;" :: "r"(saddr), "l"(gptr) : "memory")
#define CP_COMMIT() asm volatile("cp.async.commit_group;" ::: "memory")
#define CP_WAIT(n)  asm volatile("cp.async.wait_group %0;" :: "n"(n) : "memory")

__device__ __forceinline__ void mma_tf32(float* d, const uint32_t* a, const uint32_t* b) {
    asm volatile(
        "mma.sync.aligned.m16n8k8.row.col.f32.tf32.tf32.f32 "
        "{%0,%1,%2,%3}, {%4,%5,%6,%7}, {%8,%9}, {%0,%1,%2,%3};"
        : "+f"(d[0]), "+f"(d[1]), "+f"(d[2]), "+f"(d[3])
        : "r"(a[0]), "r"(a[1]), "r"(a[2]), "r"(a[3]), "r"(b[0]), "r"(b[1]));
}

// ---------------------------------------------------------------------------
// tf32 round prepass (weights only — tiny)
// ---------------------------------------------------------------------------
__global__ void round_kernel(const float4* __restrict__ in, float4* __restrict__ out, int n4) {
    int i = blockIdx.x * blockDim.x + threadIdx.x;
    int stride = gridDim.x * blockDim.x;
    for (; i < n4; i += stride) {
        float4 v = in[i];
        uint4 u = make_uint4(cvt_tf32(v.x), cvt_tf32(v.y), cvt_tf32(v.z), cvt_tf32(v.w));
        out[i] = *(float4*)&u;
    }
}

// ---------------------------------------------------------------------------
// TF32 mma.sync GEMM, cp.async 3-stage pipeline.  (R10 winner, verbatim)
// CTA 128x128, 128 threads, 4 warps (2M x 2N), warp tile 64x64.
// ---------------------------------------------------------------------------
#define BM 128
#define BN 128
#define LDS_PITCH 36
#define KCHUNKS (HIDDEN / 32)            // 16
#define T_BUF (128 * LDS_PITCH)          // 4608 floats / operand / stage
#define STAGES 3
#define DYN_SMEM_BYTES (STAGES * 2 * T_BUF * 4)   // 110592 B

template<bool CVT_A>
__global__ __launch_bounds__(128, 2)
void gemm_cp(const float* __restrict__ A,
             const float* __restrict__ W,
             const float* __restrict__ bias,
             float* __restrict__ C)
{
    extern __shared__ __align__(16) float smem[];
    const uint32_t smem_base = smem_u32(smem);
    const uint32_t sA0 = smem_base;
    const uint32_t sB0 = smem_base + STAGES * T_BUF * 4;

    const int tid  = threadIdx.x;
    const int bm   = blockIdx.y * BM;
    const int bn   = blockIdx.x * BN;
    const int lane = tid & 31;
    const int wid  = tid >> 5;
    const int m0w  = (wid & 1) * 64;
    const int n0w  = (wid >> 1) * 64;
    const int g    = lane >> 2;
    const int t    = lane & 3;

    const int r = tid >> 3;               // 0..15 (rows r + 16*i)
    const int q = tid & 7;                // 0..7

    const float* aG = A + (size_t)(bm + r) * HIDDEN + q * 4;
    const float* bG = W + (size_t)(bn + r) * HIDDEN + q * 4;
    const uint32_t aS = sA0 + (uint32_t)(r * LDS_PITCH + q * 4) * 4;
    const uint32_t bS = sB0 + (uint32_t)(r * LDS_PITCH + q * 4) * 4;

    float acc[4][8][4];
#pragma unroll
    for (int mi = 0; mi < 4; mi++)
#pragma unroll
        for (int ni = 0; ni < 8; ni++)
#pragma unroll
            for (int e = 0; e < 4; e++) acc[mi][ni][e] = 0.f;

#define ISSUE_STAGE(ck, st) do { \
    const float* _ag = aG + (ck) * 32; \
    const float* _bg = bG + (ck) * 32; \
    uint32_t _as = aS + (uint32_t)(st) * (T_BUF * 4); \
    uint32_t _bs = bS + (uint32_t)(st) * (T_BUF * 4); \
    _Pragma("unroll") \
    for (int _i = 0; _i < 8; _i++) \
        CP_ASYNC16(_as + _i * 16 * LDS_PITCH * 4, _ag + (size_t)_i * 16 * HIDDEN); \
    _Pragma("unroll") \
    for (int _i = 0; _i < 8; _i++) \
        CP_ASYNC16(_bs + _i * 16 * LDS_PITCH * 4, _bg + (size_t)_i * 16 * HIDDEN); \
    CP_COMMIT(); \
} while (0)

    ISSUE_STAGE(0, 0);
    ISSUE_STAGE(1, 1);

    uint32_t af[2][4][4], bf[2][8][2];

#define LDA(v) (CVT_A ? cvt_tf32(v) : __float_as_uint(v))

    int st = 0;
    for (int ck = 0; ck < KCHUNKS; ck++) {
        if (ck < KCHUNKS - 1) { CP_WAIT(1); } else { CP_WAIT(0); }
        __syncthreads();
        if (ck + 2 < KCHUNKS) {
            int nst = st + 2; if (nst >= STAGES) nst -= STAGES;
            ISSUE_STAGE(ck + 2, nst);
        }

        const float* cA = smem + st * T_BUF;
        const float* cB = smem + STAGES * T_BUF + st * T_BUF;

#pragma unroll
        for (int mi = 0; mi < 4; mi++) {
            const float* ap = cA + (m0w + mi * 16 + g) * LDS_PITCH + t;
            af[0][mi][0] = LDA(ap[0]);
            af[0][mi][1] = LDA(ap[8 * LDS_PITCH]);
            af[0][mi][2] = LDA(ap[4]);
            af[0][mi][3] = LDA(ap[8 * LDS_PITCH + 4]);
        }
#pragma unroll
        for (int ni = 0; ni < 8; ni++) {
            const float* bp = cB + (n0w + ni * 8 + g) * LDS_PITCH + t;
            bf[0][ni][0] = __float_as_uint(bp[0]);
            bf[0][ni][1] = __float_as_uint(bp[4]);
        }

#pragma unroll
        for (int s = 0; s < 4; s++) {
            const int cur = s & 1;
            if (s < 3) {
                const int nxt = cur ^ 1;
                const int kc = (s + 1) * 8;
#pragma unroll
                for (int mi = 0; mi < 4; mi++) {
                    const float* ap = cA + (m0w + mi * 16 + g) * LDS_PITCH + kc + t;
                    af[nxt][mi][0] = LDA(ap[0]);
                    af[nxt][mi][1] = LDA(ap[8 * LDS_PITCH]);
                    af[nxt][mi][2] = LDA(ap[4]);
                    af[nxt][mi][3] = LDA(ap[8 * LDS_PITCH + 4]);
                }
#pragma unroll
                for (int ni = 0; ni < 8; ni++) {
                    const float* bp = cB + (n0w + ni * 8 + g) * LDS_PITCH + kc + t;
                    bf[nxt][ni][0] = __float_as_uint(bp[0]);
                    bf[nxt][ni][1] = __float_as_uint(bp[4]);
                }
            }
#pragma unroll
            for (int mi = 0; mi < 4; mi++)
#pragma unroll
                for (int ni = 0; ni < 8; ni++)
                    mma_tf32(acc[mi][ni], af[cur][mi], bf[cur][ni]);
        }

        st++; if (st >= STAGES) st -= STAGES;
    }
#undef LDA

    // epilogue: bias + store
#pragma unroll
    for (int ni = 0; ni < 8; ni++) {
        const int n = bn + n0w + ni * 8 + t * 2;
        const float b0 = __ldg(&bias[n]);
        const float b1 = __ldg(&bias[n + 1]);
#pragma unroll
        for (int mi = 0; mi < 4; mi++) {
            const int m = bm + m0w + mi * 16 + g;
            float2 v0 = make_float2(acc[mi][ni][0] + b0, acc[mi][ni][1] + b1);
            float2 v1 = make_float2(acc[mi][ni][2] + b0, acc[mi][ni][3] + b1);
            *(float2*)&C[(size_t)m * HIDDEN + n]       = v0;
            *(float2*)&C[(size_t)(m + 8) * HIDDEN + n] = v1;
        }
    }
}

// ---------------------------------------------------------------------------
// warp reduction + yy precompute
// ---------------------------------------------------------------------------
__device__ __forceinline__ float warpSum(float v) {
    v += __shfl_xor_sync(0xffffffffu, v, 16);
    v += __shfl_xor_sync(0xffffffffu, v, 8);
    v += __shfl_xor_sync(0xffffffffu, v, 4);
    v += __shfl_xor_sync(0xffffffffu, v, 2);
    v += __shfl_xor_sync(0xffffffffu, v, 1);
    return v;
}

__global__ void yy_kernel(const float* __restrict__ mw) {
    const int idx  = blockIdx.x;
    const int lane = threadIdx.x;
    const float* p = mw + (size_t)idx * HIDDEN;
    float s = 0.f;
#pragma unroll
    for (int u = 0; u < 16; u++) { float v = p[u * 32 + lane]; s += v * v; }
    s = warpSum(s);
    if (lane == 0) g_yy[idx] = s;
}

// ---------------------------------------------------------------------------
// Mobius aggregation (R8/R10 NB=1 winner, verbatim): one block per batch
// element, 9 warps (one per node). Writes tf32-rounded output.
// ---------------------------------------------------------------------------
__device__ const int d_ncnt[9]   = {3, 3, 2, 3, 3, 2, 3, 3, 8};
__device__ const int d_nbr[9][8] = {
    {4, 7, 8, 0, 0, 0, 0, 0},
    {0, 6, 8, 0, 0, 0, 0, 0},
    {5, 8, 0, 0, 0, 0, 0, 0},
    {1, 4, 8, 0, 0, 0, 0, 0},
    {6, 3, 8, 0, 0, 0, 0, 0},
    {2, 8, 0, 0, 0, 0, 0, 0},
    {7, 1, 8, 0, 0, 0, 0, 0},
    {3, 0, 8, 0, 0, 0, 0, 0},
    {0, 1, 2, 3, 4, 5, 6, 7}
};

__global__ __launch_bounds__(288)
void mobius_kernel(float* __restrict__ buf,
                   const float* __restrict__ mw,
                   const float* __restrict__ curv)
{
    __shared__ __align__(16) float sh[NUM_NODES * HIDDEN];
    __shared__ float sh_xx[NUM_NODES];

    const int b   = blockIdx.x;
    const int tid = threadIdx.x;
    const float c = fabsf(curv[0]);
    float* base = buf + (size_t)b * NUM_NODES * HIDDEN;

    for (int idx = tid; idx < NUM_NODES * HIDDEN / 4; idx += 288)
        ((float4*)sh)[idx] = ((const float4*)base)[idx];
    __syncthreads();

    const int w    = tid >> 5;
    const int lane = tid & 31;

    float r[16];
    float n2 = 0.f;
#pragma unroll
    for (int u = 0; u < 16; u++) {
        r[u] = sh[w * HIDDEN + u * 32 + lane];
        n2 += r[u] * r[u];
    }
    n2 = warpSum(n2);
    float norm  = sqrtf(n2);
    float scale = tanhf(norm) / (norm + EPS);
    float rr = scale * scale * n2;
#pragma unroll
    for (int u = 0; u < 16; u++) {
        r[u] *= scale;
        sh[w * HIDDEN + u * 32 + lane] = r[u];
    }
    if (lane == 0) sh_xx[w] = rr;
    __syncthreads();

    const int cnt = d_ncnt[w];
    for (int q = 0; q < cnt; q++) {
        const int j = d_nbr[w][q];
        const float* mwp = mw + ((size_t)w * NUM_NODES + j) * HIDDEN;
        const float yy = __ldg(&g_yy[w * NUM_NODES + j]);

        float hj[16], mv[16];
        float xy = 0.f;
#pragma unroll
        for (int u = 0; u < 16; u++) {
            hj[u] = sh[j * HIDDEN + u * 32 + lane];
            mv[u] = __ldg(&mwp[u * 32 + lane]);
            xy += hj[u] * mv[u];
        }
        xy = warpSum(xy);
        const float xxj = sh_xx[j];

        const float ca  = 1.f + 2.f * c * xy + c * yy;
        const float cb  = 1.f - c * xxj;
        const float inv = 1.f / (1.f + 2.f * c * xy + c * c * xxj * yy + EPS);
        const float tt  = inv * inv * (ca * ca * xxj + 2.f * ca * cb * xy + cb * cb * yy);

        float t[16];
        float rt = 0.f;
#pragma unroll
        for (int u = 0; u < 16; u++) {
            t[u] = (ca * hj[u] + cb * mv[u]) * inv;
            rt += r[u] * t[u];
        }
        rt = warpSum(rt);

        const float ca2  = 1.f + 2.f * c * rt + c * tt;
        const float cb2  = 1.f - c * rr;
        const float inv2 = 1.f / (1.f + 2.f * c * rt + c * c * rr * tt + EPS);
#pragma unroll
        for (int u = 0; u < 16; u++)
            r[u] = (ca2 * r[u] + cb2 * t[u]) * inv2;
        rr = inv2 * inv2 * (ca2 * ca2 * rr + 2.f * ca2 * cb2 * rt + cb2 * cb2 * tt);
    }

    // store tf32-rounded (GEMM2 consumes without further conversion)
    float* dst = base + (size_t)w * HIDDEN;
#pragma unroll
    for (int u = 0; u < 16; u++)
        dst[u * 32 + lane] = __uint_as_float(cvt_tf32(r[u]));
}

// ---------------------------------------------------------------------------
// kernel_launch: 4 independent batch chunks, each G1->mobius->G2 on its own
// forked stream (graph-capturable fork/join via events). Mobius of one chunk
// overlaps GEMMs of the others.
// ---------------------------------------------------------------------------
extern "C" void kernel_launch(void* const* d_in, const int* in_sizes, int n_in,
                              void* d_out, int out_size)
{
    const float* nf     = (const float*)d_in[0];
    const float* curv   = (const float*)d_in[1];
    const float* to_w   = (const float*)d_in[2];
    const float* to_b   = (const float*)d_in[3];
    const float* from_w = (const float*)d_in[4];
    const float* from_b = (const float*)d_in[5];
    const float* mw     = (const float*)d_in[6];
    float* out = (float*)d_out;

    float *scratch, *w1, *w2;
    cudaGetSymbolAddress((void**)&scratch, g_scratch);
    cudaGetSymbolAddress((void**)&w1,      g_w1);
    cudaGetSymbolAddress((void**)&w2,      g_w2);

    cudaFuncSetAttribute(gemm_cp<true>,  cudaFuncAttributeMaxDynamicSharedMemorySize,
                         DYN_SMEM_BYTES);
    cudaFuncSetAttribute(gemm_cp<false>, cudaFuncAttributeMaxDynamicSharedMemorySize,
                         DYN_SMEM_BYTES);

    // Prepasses on the origin (capture) stream.
    round_kernel<<<128, 256>>>((const float4*)to_w,   (float4*)w1, HIDDEN * HIDDEN / 4);
    round_kernel<<<128, 256>>>((const float4*)from_w, (float4*)w2, HIDDEN * HIDDEN / 4);
    yy_kernel<<<NUM_NODES * NUM_NODES, 32>>>(mw);

    // Fork NCHUNKS streams off the origin stream.
    cudaStream_t s[NCHUNKS];
    cudaEvent_t  eFork, eJoin[NCHUNKS];
    cudaEventCreateWithFlags(&eFork, cudaEventDisableTiming);
    cudaEventRecord(eFork, 0);
    for (int k = 0; k < NCHUNKS; k++) {
        cudaStreamCreateWithFlags(&s[k], cudaStreamNonBlocking);
        cudaEventCreateWithFlags(&eJoin[k], cudaEventDisableTiming);
        cudaStreamWaitEvent(s[k], eFork, 0);
    }

    dim3 gg(HIDDEN / BN, ROWS_PER_CHUNK / BM);   // (4, 144)

    for (int k = 0; k < NCHUNKS; k++) {
        const size_t rowOff = (size_t)k * ROWS_PER_CHUNK;
        const float* aPtr = nf      + rowOff * HIDDEN;
        float*       sPtr = scratch + rowOff * HIDDEN;
        float*       oPtr = out     + rowOff * HIDDEN;

        // 1) x_proj chunk  (A rounded in-kernel)
        gemm_cp<true><<<gg, 128, DYN_SMEM_BYTES, s[k]>>>(aPtr, w1, to_b, sPtr);
        // 2) mobius chunk (in place, writes tf32-rounded)
        mobius_kernel<<<BATCH_PER_CHUNK, 288, 0, s[k]>>>(sPtr, mw, curv);
        // 3) output chunk
        gemm_cp<false><<<gg, 128, DYN_SMEM_BYTES, s[k]>>>(sPtr, w2, from_b, oPtr);

        cudaEventRecord(eJoin[k], s[k]);
    }

    // Join all chunk streams back into the origin stream.
    for (int k = 0; k < NCHUNKS; k++)
        cudaStreamWaitEvent(0, eJoin[k], 0);

    for (int k = 0; k < NCHUNKS; k++) {
        cudaStreamDestroy(s[k]);
        cudaEventDestroy(eJoin[k]);
    }
    cudaEventDestroy(eFork);
}

// round 12
// speedup vs baseline: 1.1444x; 1.0181x over previous
#include <cuda_runtime.h>
#include <cuda_bf16.h>
#include <math.h>
#include <cstdint>

#define NUM_NODES 9
#define HIDDEN    512
#define BATCH     8192
#define M_ROWS    (BATCH * NUM_NODES)   // 73728
#define EPS       1e-8f

#define NCHUNKS         4
#define BATCH_PER_CHUNK (BATCH / NCHUNKS)              // 2048
#define ROWS_PER_CHUNK  (BATCH_PER_CHUNK * NUM_NODES)  // 18432 = 144 * 128

// Scratch buffers (device globals; no dynamic alloc allowed).
__device__ float g_scratch[(size_t)M_ROWS * HIDDEN];   // x_proj -> h -> mobius out (tf32-rounded)
__device__ float g_w1[HIDDEN * HIDDEN];                // tf32-rounded to_w
__device__ float g_w2[HIDDEN * HIDDEN];                // tf32-rounded from_w
__device__ float g_yy[NUM_NODES * NUM_NODES];          // ||mw[i][j]||^2

__device__ __forceinline__ uint32_t smem_u32(const void* p) {
    uint32_t a;
    asm("{ .reg .u64 t; cvta.to.shared.u64 t, %1; cvt.u32.u64 %0, t; }" : "=r"(a) : "l"(p));
    return a;
}
__device__ __forceinline__ uint32_t cvt_tf32(float f) {
    uint32_t u;
    asm("cvt.rna.tf32.f32 %0, %1;" : "=r"(u) : "f"(f));
    return u;
}

#define CP_ASYNC16(saddr, gptr) \
    asm volatile("cp.async.cg.shared.global [%0], [%1], 16;" :: "r"(saddr), "l"(gptr) : "memory")
#define CP_COMMIT() asm volatile("cp.async.commit_group;" ::: "memory")
#define CP_WAIT(n)  asm volatile("cp.async.wait_group %0;" :: "n"(n) : "memory")

__device__ __forceinline__ void mma_tf32(float* d, const uint32_t* a, const uint32_t* b) {
    asm volatile(
        "mma.sync.aligned.m16n8k8.row.col.f32.tf32.tf32.f32 "
        "{%0,%1,%2,%3}, {%4,%5,%6,%7}, {%8,%9}, {%0,%1,%2,%3};"
        : "+f"(d[0]), "+f"(d[1]), "+f"(d[2]), "+f"(d[3])
        : "r"(a[0]), "r"(a[1]), "r"(a[2]), "r"(a[3]), "r"(b[0]), "r"(b[1]));
}

// ---------------------------------------------------------------------------
// tf32 round prepass (weights only — tiny)
// ---------------------------------------------------------------------------
__global__ void round_kernel(const float4* __restrict__ in, float4* __restrict__ out, int n4) {
    int i = blockIdx.x * blockDim.x + threadIdx.x;
    int stride = gridDim.x * blockDim.x;
    for (; i < n4; i += stride) {
        float4 v = in[i];
        uint4 u = make_uint4(cvt_tf32(v.x), cvt_tf32(v.y), cvt_tf32(v.z), cvt_tf32(v.w));
        out[i] = *(float4*)&u;
    }
}

// ---------------------------------------------------------------------------
// TF32 mma.sync GEMM, cp.async 2-stage pipeline.
// CTA 128x128, 128 threads, 4 warps (2M x 2N), warp tile 64x64.
// 73.7 KB smem/CTA -> 2 CTAs/SM leaves ~80 KB so mobius blocks co-reside.
// Per-iter order: WAIT(0) -> sync -> issue(ck+1) -> compute(ck):
// copy(ck+1) overlaps compute(ck); buffer(ck+1) is free at the barrier.
// ---------------------------------------------------------------------------
#define BM 128
#define BN 128
#define LDS_PITCH 36
#define KCHUNKS (HIDDEN / 32)            // 16
#define T_BUF (128 * LDS_PITCH)          // 4608 floats / operand / stage
#define STAGES 2
#define DYN_SMEM_BYTES (STAGES * 2 * T_BUF * 4)   // 73728 B

template<bool CVT_A>
__global__ __launch_bounds__(128, 2)
void gemm_cp(const float* __restrict__ A,
             const float* __restrict__ W,
             const float* __restrict__ bias,
             float* __restrict__ C)
{
    extern __shared__ __align__(16) float smem[];
    const uint32_t smem_base = smem_u32(smem);
    const uint32_t sA0 = smem_base;
    const uint32_t sB0 = smem_base + STAGES * T_BUF * 4;

    const int tid  = threadIdx.x;
    const int bm   = blockIdx.y * BM;
    const int bn   = blockIdx.x * BN;
    const int lane = tid & 31;
    const int wid  = tid >> 5;
    const int m0w  = (wid & 1) * 64;
    const int n0w  = (wid >> 1) * 64;
    const int g    = lane >> 2;
    const int t    = lane & 3;

    const int r = tid >> 3;               // 0..15 (rows r + 16*i)
    const int q = tid & 7;                // 0..7

    const float* aG = A + (size_t)(bm + r) * HIDDEN + q * 4;
    const float* bG = W + (size_t)(bn + r) * HIDDEN + q * 4;
    const uint32_t aS = sA0 + (uint32_t)(r * LDS_PITCH + q * 4) * 4;
    const uint32_t bS = sB0 + (uint32_t)(r * LDS_PITCH + q * 4) * 4;

    float acc[4][8][4];
#pragma unroll
    for (int mi = 0; mi < 4; mi++)
#pragma unroll
        for (int ni = 0; ni < 8; ni++)
#pragma unroll
            for (int e = 0; e < 4; e++) acc[mi][ni][e] = 0.f;

#define ISSUE_STAGE(ck, st) do { \
    const float* _ag = aG + (ck) * 32; \
    const float* _bg = bG + (ck) * 32; \
    uint32_t _as = aS + (uint32_t)(st) * (T_BUF * 4); \
    uint32_t _bs = bS + (uint32_t)(st) * (T_BUF * 4); \
    _Pragma("unroll") \
    for (int _i = 0; _i < 8; _i++) \
        CP_ASYNC16(_as + _i * 16 * LDS_PITCH * 4, _ag + (size_t)_i * 16 * HIDDEN); \
    _Pragma("unroll") \
    for (int _i = 0; _i < 8; _i++) \
        CP_ASYNC16(_bs + _i * 16 * LDS_PITCH * 4, _bg + (size_t)_i * 16 * HIDDEN); \
    CP_COMMIT(); \
} while (0)

    ISSUE_STAGE(0, 0);

    uint32_t af[2][4][4], bf[2][8][2];

#define LDA(v) (CVT_A ? cvt_tf32(v) : __float_as_uint(v))

    for (int ck = 0; ck < KCHUNKS; ck++) {
        const int st = ck & 1;
        CP_WAIT(0);                 // only group ck is outstanding here
        __syncthreads();            // everyone done with buffer (ck+1)&1 from iter ck-1
        if (ck + 1 < KCHUNKS)
            ISSUE_STAGE(ck + 1, st ^ 1);   // overlaps compute below

        const float* cA = smem + st * T_BUF;
        const float* cB = smem + STAGES * T_BUF + st * T_BUF;

#pragma unroll
        for (int mi = 0; mi < 4; mi++) {
            const float* ap = cA + (m0w + mi * 16 + g) * LDS_PITCH + t;
            af[0][mi][0] = LDA(ap[0]);
            af[0][mi][1] = LDA(ap[8 * LDS_PITCH]);
            af[0][mi][2] = LDA(ap[4]);
            af[0][mi][3] = LDA(ap[8 * LDS_PITCH + 4]);
        }
#pragma unroll
        for (int ni = 0; ni < 8; ni++) {
            const float* bp = cB + (n0w + ni * 8 + g) * LDS_PITCH + t;
            bf[0][ni][0] = __float_as_uint(bp[0]);
            bf[0][ni][1] = __float_as_uint(bp[4]);
        }

#pragma unroll
        for (int s = 0; s < 4; s++) {
            const int cur = s & 1;
            if (s < 3) {
                const int nxt = cur ^ 1;
                const int kc = (s + 1) * 8;
#pragma unroll
                for (int mi = 0; mi < 4; mi++) {
                    const float* ap = cA + (m0w + mi * 16 + g) * LDS_PITCH + kc + t;
                    af[nxt][mi][0] = LDA(ap[0]);
                    af[nxt][mi][1] = LDA(ap[8 * LDS_PITCH]);
                    af[nxt][mi][2] = LDA(ap[4]);
                    af[nxt][mi][3] = LDA(ap[8 * LDS_PITCH + 4]);
                }
#pragma unroll
                for (int ni = 0; ni < 8; ni++) {
                    const float* bp = cB + (n0w + ni * 8 + g) * LDS_PITCH + kc + t;
                    bf[nxt][ni][0] = __float_as_uint(bp[0]);
                    bf[nxt][ni][1] = __float_as_uint(bp[4]);
                }
            }
#pragma unroll
            for (int mi = 0; mi < 4; mi++)
#pragma unroll
                for (int ni = 0; ni < 8; ni++)
                    mma_tf32(acc[mi][ni], af[cur][mi], bf[cur][ni]);
        }
    }
#undef LDA

    // epilogue: bias + store
#pragma unroll
    for (int ni = 0; ni < 8; ni++) {
        const int n = bn + n0w + ni * 8 + t * 2;
        const float b0 = __ldg(&bias[n]);
        const float b1 = __ldg(&bias[n + 1]);
#pragma unroll
        for (int mi = 0; mi < 4; mi++) {
            const int m = bm + m0w + mi * 16 + g;
            float2 v0 = make_float2(acc[mi][ni][0] + b0, acc[mi][ni][1] + b1);
            float2 v1 = make_float2(acc[mi][ni][2] + b0, acc[mi][ni][3] + b1);
            *(float2*)&C[(size_t)m * HIDDEN + n]       = v0;
            *(float2*)&C[(size_t)(m + 8) * HIDDEN + n] = v1;
        }
    }
}

// ---------------------------------------------------------------------------
// warp reduction + yy precompute
// ---------------------------------------------------------------------------
__device__ __forceinline__ float warpSum(float v) {
    v += __shfl_xor_sync(0xffffffffu, v, 16);
    v += __shfl_xor_sync(0xffffffffu, v, 8);
    v += __shfl_xor_sync(0xffffffffu, v, 4);
    v += __shfl_xor_sync(0xffffffffu, v, 2);
    v += __shfl_xor_sync(0xffffffffu, v, 1);
    return v;
}

__global__ void yy_kernel(const float* __restrict__ mw) {
    const int idx  = blockIdx.x;
    const int lane = threadIdx.x;
    const float* p = mw + (size_t)idx * HIDDEN;
    float s = 0.f;
#pragma unroll
    for (int u = 0; u < 16; u++) { float v = p[u * 32 + lane]; s += v * v; }
    s = warpSum(s);
    if (lane == 0) g_yy[idx] = s;
}

// ---------------------------------------------------------------------------
// Mobius aggregation (NB=1 winner, verbatim): one block per batch element,
// 9 warps (one per node). Writes tf32-rounded output.
// ---------------------------------------------------------------------------
__device__ const int d_ncnt[9]   = {3, 3, 2, 3, 3, 2, 3, 3, 8};
__device__ const int d_nbr[9][8] = {
    {4, 7, 8, 0, 0, 0, 0, 0},
    {0, 6, 8, 0, 0, 0, 0, 0},
    {5, 8, 0, 0, 0, 0, 0, 0},
    {1, 4, 8, 0, 0, 0, 0, 0},
    {6, 3, 8, 0, 0, 0, 0, 0},
    {2, 8, 0, 0, 0, 0, 0, 0},
    {7, 1, 8, 0, 0, 0, 0, 0},
    {3, 0, 8, 0, 0, 0, 0, 0},
    {0, 1, 2, 3, 4, 5, 6, 7}
};

__global__ __launch_bounds__(288)
void mobius_kernel(float* __restrict__ buf,
                   const float* __restrict__ mw,
                   const float* __restrict__ curv)
{
    __shared__ __align__(16) float sh[NUM_NODES * HIDDEN];
    __shared__ float sh_xx[NUM_NODES];

    const int b   = blockIdx.x;
    const int tid = threadIdx.x;
    const float c = fabsf(curv[0]);
    float* base = buf + (size_t)b * NUM_NODES * HIDDEN;

    for (int idx = tid; idx < NUM_NODES * HIDDEN / 4; idx += 288)
        ((float4*)sh)[idx] = ((const float4*)base)[idx];
    __syncthreads();

    const int w    = tid >> 5;
    const int lane = tid & 31;

    float r[16];
    float n2 = 0.f;
#pragma unroll
    for (int u = 0; u < 16; u++) {
        r[u] = sh[w * HIDDEN + u * 32 + lane];
        n2 += r[u] * r[u];
    }
    n2 = warpSum(n2);
    float norm  = sqrtf(n2);
    float scale = tanhf(norm) / (norm + EPS);
    float rr = scale * scale * n2;
#pragma unroll
    for (int u = 0; u < 16; u++) {
        r[u] *= scale;
        sh[w * HIDDEN + u * 32 + lane] = r[u];
    }
    if (lane == 0) sh_xx[w] = rr;
    __syncthreads();

    const int cnt = d_ncnt[w];
    for (int q = 0; q < cnt; q++) {
        const int j = d_nbr[w][q];
        const float* mwp = mw + ((size_t)w * NUM_NODES + j) * HIDDEN;
        const float yy = __ldg(&g_yy[w * NUM_NODES + j]);

        float hj[16], mv[16];
        float xy = 0.f;
#pragma unroll
        for (int u = 0; u < 16; u++) {
            hj[u] = sh[j * HIDDEN + u * 32 + lane];
            mv[u] = __ldg(&mwp[u * 32 + lane]);
            xy += hj[u] * mv[u];
        }
        xy = warpSum(xy);
        const float xxj = sh_xx[j];

        const float ca  = 1.f + 2.f * c * xy + c * yy;
        const float cb  = 1.f - c * xxj;
        const float inv = 1.f / (1.f + 2.f * c * xy + c * c * xxj * yy + EPS);
        const float tt  = inv * inv * (ca * ca * xxj + 2.f * ca * cb * xy + cb * cb * yy);

        float t[16];
        float rt = 0.f;
#pragma unroll
        for (int u = 0; u < 16; u++) {
            t[u] = (ca * hj[u] + cb * mv[u]) * inv;
            rt += r[u] * t[u];
        }
        rt = warpSum(rt);

        const float ca2  = 1.f + 2.f * c * rt + c * tt;
        const float cb2  = 1.f - c * rr;
        const float inv2 = 1.f / (1.f + 2.f * c * rt + c * c * rr * tt + EPS);
#pragma unroll
        for (int u = 0; u < 16; u++)
            r[u] = (ca2 * r[u] + cb2 * t[u]) * inv2;
        rr = inv2 * inv2 * (ca2 * ca2 * rr + 2.f * ca2 * cb2 * rt + cb2 * cb2 * tt);
    }

    // store tf32-rounded (GEMM2 consumes without further conversion)
    float* dst = base + (size_t)w * HIDDEN;
#pragma unroll
    for (int u = 0; u < 16; u++)
        dst[u * 32 + lane] = __uint_as_float(cvt_tf32(r[u]));
}

// ---------------------------------------------------------------------------
// kernel_launch: 4 independent batch chunks on forked streams; with the
// 2-stage GEMM (73.7 KB smem) mobius blocks co-reside with GEMM CTAs.
// ---------------------------------------------------------------------------
extern "C" void kernel_launch(void* const* d_in, const int* in_sizes, int n_in,
                              void* d_out, int out_size)
{
    const float* nf     = (const float*)d_in[0];
    const float* curv   = (const float*)d_in[1];
    const float* to_w   = (const float*)d_in[2];
    const float* to_b   = (const float*)d_in[3];
    const float* from_w = (const float*)d_in[4];
    const float* from_b = (const float*)d_in[5];
    const float* mw     = (const float*)d_in[6];
    float* out = (float*)d_out;

    float *scratch, *w1, *w2;
    cudaGetSymbolAddress((void**)&scratch, g_scratch);
    cudaGetSymbolAddress((void**)&w1,      g_w1);
    cudaGetSymbolAddress((void**)&w2,      g_w2);

    cudaFuncSetAttribute(gemm_cp<true>,  cudaFuncAttributeMaxDynamicSharedMemorySize,
                         DYN_SMEM_BYTES);
    cudaFuncSetAttribute(gemm_cp<false>, cudaFuncAttributeMaxDynamicSharedMemorySize,
                         DYN_SMEM_BYTES);

    // Prepasses on the origin (capture) stream.
    round_kernel<<<128, 256>>>((const float4*)to_w,   (float4*)w1, HIDDEN * HIDDEN / 4);
    round_kernel<<<128, 256>>>((const float4*)from_w, (float4*)w2, HIDDEN * HIDDEN / 4);
    yy_kernel<<<NUM_NODES * NUM_NODES, 32>>>(mw);

    // Fork NCHUNKS streams off the origin stream.
    cudaStream_t s[NCHUNKS];
    cudaEvent_t  eFork, eJoin[NCHUNKS];
    cudaEventCreateWithFlags(&eFork, cudaEventDisableTiming);
    cudaEventRecord(eFork, 0);
    for (int k = 0; k < NCHUNKS; k++) {
        cudaStreamCreateWithFlags(&s[k], cudaStreamNonBlocking);
        cudaEventCreateWithFlags(&eJoin[k], cudaEventDisableTiming);
        cudaStreamWaitEvent(s[k], eFork, 0);
    }

    dim3 gg(HIDDEN / BN, ROWS_PER_CHUNK / BM);   // (4, 144)

    for (int k = 0; k < NCHUNKS; k++) {
        const size_t rowOff = (size_t)k * ROWS_PER_CHUNK;
        const float* aPtr = nf      + rowOff * HIDDEN;
        float*       sPtr = scratch + rowOff * HIDDEN;
        float*       oPtr = out     + rowOff * HIDDEN;

        gemm_cp<true><<<gg, 128, DYN_SMEM_BYTES, s[k]>>>(aPtr, w1, to_b, sPtr);
        mobius_kernel<<<BATCH_PER_CHUNK, 288, 0, s[k]>>>(sPtr, mw, curv);
        gemm_cp<false><<<gg, 128, DYN_SMEM_BYTES, s[k]>>>(sPtr, w2, from_b, oPtr);

        cudaEventRecord(eJoin[k], s[k]);
    }

    for (int k = 0; k < NCHUNKS; k++)
        cudaStreamWaitEvent(0, eJoin[k], 0);

    for (int k = 0; k < NCHUNKS; k++) {
        cudaStreamDestroy(s[k]);
        cudaEventDestroy(eJoin[k]);
    }
    cudaEventDestroy(eFork);
}

// round 13
// speedup vs baseline: 1.1531x; 1.0075x over previous
#include <cuda_runtime.h>
#include <cuda_bf16.h>
#include <math.h>
#include <cstdint>

#define NUM_NODES 9
#define HIDDEN    512
#define BATCH     8192
#define M_ROWS    (BATCH * NUM_NODES)   // 73728
#define EPS       1e-8f

#define NCHUNKS         4
#define BATCH_PER_CHUNK (BATCH / NCHUNKS)              // 2048
#define ROWS_PER_CHUNK  (BATCH_PER_CHUNK * NUM_NODES)  // 18432 = 144 * 128

// Scratch buffers (device globals; no dynamic alloc allowed).
__device__ float g_scratch[(size_t)M_ROWS * HIDDEN];   // x_proj -> h -> mobius out (tf32-rounded)
__device__ float g_w1[HIDDEN * HIDDEN];                // tf32-rounded to_w
__device__ float g_w2[HIDDEN * HIDDEN];                // tf32-rounded from_w
__device__ float g_yy[NUM_NODES * NUM_NODES];          // ||mw[i][j]||^2

__device__ __forceinline__ uint32_t smem_u32(const void* p) {
    uint32_t a;
    asm("{ .reg .u64 t; cvta.to.shared.u64 t, %1; cvt.u32.u64 %0, t; }" : "=r"(a) : "l"(p));
    return a;
}
__device__ __forceinline__ uint32_t cvt_tf32(float f) {
    uint32_t u;
    asm("cvt.rna.tf32.f32 %0, %1;" : "=r"(u) : "f"(f));
    return u;
}

#define CP_ASYNC16(saddr, gptr) \
    asm volatile("cp.async.cg.shared.global [%0], [%1], 16;" :: "r"(saddr), "l"(gptr) : "memory")
#define CP_COMMIT() asm volatile("cp.async.commit_group;" ::: "memory")
#define CP_WAIT(n)  asm volatile("cp.async.wait_group %0;" :: "n"(n) : "memory")

__device__ __forceinline__ void mma_tf32(float* d, const uint32_t* a, const uint32_t* b) {
    asm volatile(
        "mma.sync.aligned.m16n8k8.row.col.f32.tf32.tf32.f32 "
        "{%0,%1,%2,%3}, {%4,%5,%6,%7}, {%8,%9}, {%0,%1,%2,%3};"
        : "+f"(d[0]), "+f"(d[1]), "+f"(d[2]), "+f"(d[3])
        : "r"(a[0]), "r"(a[1]), "r"(a[2]), "r"(a[3]), "r"(b[0]), "r"(b[1]));
}

// ---------------------------------------------------------------------------
// tf32 round prepass (weights only — tiny)
// ---------------------------------------------------------------------------
__global__ void round_kernel(const float4* __restrict__ in, float4* __restrict__ out, int n4) {
    int i = blockIdx.x * blockDim.x + threadIdx.x;
    int stride = gridDim.x * blockDim.x;
    for (; i < n4; i += stride) {
        float4 v = in[i];
        uint4 u = make_uint4(cvt_tf32(v.x), cvt_tf32(v.y), cvt_tf32(v.z), cvt_tf32(v.w));
        out[i] = *(float4*)&u;
    }
}

// ---------------------------------------------------------------------------
// TF32 mma.sync GEMM, cp.async 2-stage pipeline.  (R12 winner, verbatim)
// CTA 128x128, 128 threads, 4 warps (2M x 2N), warp tile 64x64.
// ---------------------------------------------------------------------------
#define BM 128
#define BN 128
#define LDS_PITCH 36
#define KCHUNKS (HIDDEN / 32)            // 16
#define T_BUF (128 * LDS_PITCH)          // 4608 floats / operand / stage
#define STAGES 2
#define DYN_SMEM_BYTES (STAGES * 2 * T_BUF * 4)   // 73728 B

template<bool CVT_A>
__global__ __launch_bounds__(128, 2)
void gemm_cp(const float* __restrict__ A,
             const float* __restrict__ W,
             const float* __restrict__ bias,
             float* __restrict__ C)
{
    extern __shared__ __align__(16) float smem[];
    const uint32_t smem_base = smem_u32(smem);
    const uint32_t sA0 = smem_base;
    const uint32_t sB0 = smem_base + STAGES * T_BUF * 4;

    const int tid  = threadIdx.x;
    const int bm   = blockIdx.y * BM;
    const int bn   = blockIdx.x * BN;
    const int lane = tid & 31;
    const int wid  = tid >> 5;
    const int m0w  = (wid & 1) * 64;
    const int n0w  = (wid >> 1) * 64;
    const int g    = lane >> 2;
    const int t    = lane & 3;

    const int r = tid >> 3;               // 0..15 (rows r + 16*i)
    const int q = tid & 7;                // 0..7

    const float* aG = A + (size_t)(bm + r) * HIDDEN + q * 4;
    const float* bG = W + (size_t)(bn + r) * HIDDEN + q * 4;
    const uint32_t aS = sA0 + (uint32_t)(r * LDS_PITCH + q * 4) * 4;
    const uint32_t bS = sB0 + (uint32_t)(r * LDS_PITCH + q * 4) * 4;

    float acc[4][8][4];
#pragma unroll
    for (int mi = 0; mi < 4; mi++)
#pragma unroll
        for (int ni = 0; ni < 8; ni++)
#pragma unroll
            for (int e = 0; e < 4; e++) acc[mi][ni][e] = 0.f;

#define ISSUE_STAGE(ck, st) do { \
    const float* _ag = aG + (ck) * 32; \
    const float* _bg = bG + (ck) * 32; \
    uint32_t _as = aS + (uint32_t)(st) * (T_BUF * 4); \
    uint32_t _bs = bS + (uint32_t)(st) * (T_BUF * 4); \
    _Pragma("unroll") \
    for (int _i = 0; _i < 8; _i++) \
        CP_ASYNC16(_as + _i * 16 * LDS_PITCH * 4, _ag + (size_t)_i * 16 * HIDDEN); \
    _Pragma("unroll") \
    for (int _i = 0; _i < 8; _i++) \
        CP_ASYNC16(_bs + _i * 16 * LDS_PITCH * 4, _bg + (size_t)_i * 16 * HIDDEN); \
    CP_COMMIT(); \
} while (0)

    ISSUE_STAGE(0, 0);

    uint32_t af[2][4][4], bf[2][8][2];

#define LDA(v) (CVT_A ? cvt_tf32(v) : __float_as_uint(v))

    for (int ck = 0; ck < KCHUNKS; ck++) {
        const int st = ck & 1;
        CP_WAIT(0);
        __syncthreads();
        if (ck + 1 < KCHUNKS)
            ISSUE_STAGE(ck + 1, st ^ 1);

        const float* cA = smem + st * T_BUF;
        const float* cB = smem + STAGES * T_BUF + st * T_BUF;

#pragma unroll
        for (int mi = 0; mi < 4; mi++) {
            const float* ap = cA + (m0w + mi * 16 + g) * LDS_PITCH + t;
            af[0][mi][0] = LDA(ap[0]);
            af[0][mi][1] = LDA(ap[8 * LDS_PITCH]);
            af[0][mi][2] = LDA(ap[4]);
            af[0][mi][3] = LDA(ap[8 * LDS_PITCH + 4]);
        }
#pragma unroll
        for (int ni = 0; ni < 8; ni++) {
            const float* bp = cB + (n0w + ni * 8 + g) * LDS_PITCH + t;
            bf[0][ni][0] = __float_as_uint(bp[0]);
            bf[0][ni][1] = __float_as_uint(bp[4]);
        }

#pragma unroll
        for (int s = 0; s < 4; s++) {
            const int cur = s & 1;
            if (s < 3) {
                const int nxt = cur ^ 1;
                const int kc = (s + 1) * 8;
#pragma unroll
                for (int mi = 0; mi < 4; mi++) {
                    const float* ap = cA + (m0w + mi * 16 + g) * LDS_PITCH + kc + t;
                    af[nxt][mi][0] = LDA(ap[0]);
                    af[nxt][mi][1] = LDA(ap[8 * LDS_PITCH]);
                    af[nxt][mi][2] = LDA(ap[4]);
                    af[nxt][mi][3] = LDA(ap[8 * LDS_PITCH + 4]);
                }
#pragma unroll
                for (int ni = 0; ni < 8; ni++) {
                    const float* bp = cB + (n0w + ni * 8 + g) * LDS_PITCH + kc + t;
                    bf[nxt][ni][0] = __float_as_uint(bp[0]);
                    bf[nxt][ni][1] = __float_as_uint(bp[4]);
                }
            }
#pragma unroll
            for (int mi = 0; mi < 4; mi++)
#pragma unroll
                for (int ni = 0; ni < 8; ni++)
                    mma_tf32(acc[mi][ni], af[cur][mi], bf[cur][ni]);
        }
    }
#undef LDA

    // epilogue: bias + store
#pragma unroll
    for (int ni = 0; ni < 8; ni++) {
        const int n = bn + n0w + ni * 8 + t * 2;
        const float b0 = __ldg(&bias[n]);
        const float b1 = __ldg(&bias[n + 1]);
#pragma unroll
        for (int mi = 0; mi < 4; mi++) {
            const int m = bm + m0w + mi * 16 + g;
            float2 v0 = make_float2(acc[mi][ni][0] + b0, acc[mi][ni][1] + b1);
            float2 v1 = make_float2(acc[mi][ni][2] + b0, acc[mi][ni][3] + b1);
            *(float2*)&C[(size_t)m * HIDDEN + n]       = v0;
            *(float2*)&C[(size_t)(m + 8) * HIDDEN + n] = v1;
        }
    }
}

// ---------------------------------------------------------------------------
// warp reduction + yy precompute
// ---------------------------------------------------------------------------
__device__ __forceinline__ float warpSum(float v) {
    v += __shfl_xor_sync(0xffffffffu, v, 16);
    v += __shfl_xor_sync(0xffffffffu, v, 8);
    v += __shfl_xor_sync(0xffffffffu, v, 4);
    v += __shfl_xor_sync(0xffffffffu, v, 2);
    v += __shfl_xor_sync(0xffffffffu, v, 1);
    return v;
}

__global__ void yy_kernel(const float* __restrict__ mw) {
    const int idx  = blockIdx.x;
    const int lane = threadIdx.x;
    const float* p = mw + (size_t)idx * HIDDEN;
    float s = 0.f;
#pragma unroll
    for (int u = 0; u < 16; u++) { float v = p[u * 32 + lane]; s += v * v; }
    s = warpSum(s);
    if (lane == 0) g_yy[idx] = s;
}

// ---------------------------------------------------------------------------
// Mobius aggregation (NB=1 winner, verbatim): one block per batch element,
// 9 warps (one per node). Writes tf32-rounded output.
// ---------------------------------------------------------------------------
__device__ const int d_ncnt[9]   = {3, 3, 2, 3, 3, 2, 3, 3, 8};
__device__ const int d_nbr[9][8] = {
    {4, 7, 8, 0, 0, 0, 0, 0},
    {0, 6, 8, 0, 0, 0, 0, 0},
    {5, 8, 0, 0, 0, 0, 0, 0},
    {1, 4, 8, 0, 0, 0, 0, 0},
    {6, 3, 8, 0, 0, 0, 0, 0},
    {2, 8, 0, 0, 0, 0, 0, 0},
    {7, 1, 8, 0, 0, 0, 0, 0},
    {3, 0, 8, 0, 0, 0, 0, 0},
    {0, 1, 2, 3, 4, 5, 6, 7}
};

__global__ __launch_bounds__(288)
void mobius_kernel(float* __restrict__ buf,
                   const float* __restrict__ mw,
                   const float* __restrict__ curv)
{
    __shared__ __align__(16) float sh[NUM_NODES * HIDDEN];
    __shared__ float sh_xx[NUM_NODES];

    const int b   = blockIdx.x;
    const int tid = threadIdx.x;
    const float c = fabsf(curv[0]);
    float* base = buf + (size_t)b * NUM_NODES * HIDDEN;

    for (int idx = tid; idx < NUM_NODES * HIDDEN / 4; idx += 288)
        ((float4*)sh)[idx] = ((const float4*)base)[idx];
    __syncthreads();

    const int w    = tid >> 5;
    const int lane = tid & 31;

    float r[16];
    float n2 = 0.f;
#pragma unroll
    for (int u = 0; u < 16; u++) {
        r[u] = sh[w * HIDDEN + u * 32 + lane];
        n2 += r[u] * r[u];
    }
    n2 = warpSum(n2);
    float norm  = sqrtf(n2);
    float scale = tanhf(norm) / (norm + EPS);
    float rr = scale * scale * n2;
#pragma unroll
    for (int u = 0; u < 16; u++) {
        r[u] *= scale;
        sh[w * HIDDEN + u * 32 + lane] = r[u];
    }
    if (lane == 0) sh_xx[w] = rr;
    __syncthreads();

    const int cnt = d_ncnt[w];
    for (int q = 0; q < cnt; q++) {
        const int j = d_nbr[w][q];
        const float* mwp = mw + ((size_t)w * NUM_NODES + j) * HIDDEN;
        const float yy = __ldg(&g_yy[w * NUM_NODES + j]);

        float hj[16], mv[16];
        float xy = 0.f;
#pragma unroll
        for (int u = 0; u < 16; u++) {
            hj[u] = sh[j * HIDDEN + u * 32 + lane];
            mv[u] = __ldg(&mwp[u * 32 + lane]);
            xy += hj[u] * mv[u];
        }
        xy = warpSum(xy);
        const float xxj = sh_xx[j];

        const float ca  = 1.f + 2.f * c * xy + c * yy;
        const float cb  = 1.f - c * xxj;
        const float inv = 1.f / (1.f + 2.f * c * xy + c * c * xxj * yy + EPS);
        const float tt  = inv * inv * (ca * ca * xxj + 2.f * ca * cb * xy + cb * cb * yy);

        float t[16];
        float rt = 0.f;
#pragma unroll
        for (int u = 0; u < 16; u++) {
            t[u] = (ca * hj[u] + cb * mv[u]) * inv;
            rt += r[u] * t[u];
        }
        rt = warpSum(rt);

        const float ca2  = 1.f + 2.f * c * rt + c * tt;
        const float cb2  = 1.f - c * rr;
        const float inv2 = 1.f / (1.f + 2.f * c * rt + c * c * rr * tt + EPS);
#pragma unroll
        for (int u = 0; u < 16; u++)
            r[u] = (ca2 * r[u] + cb2 * t[u]) * inv2;
        rr = inv2 * inv2 * (ca2 * ca2 * rr + 2.f * ca2 * cb2 * rt + cb2 * cb2 * tt);
    }

    // store tf32-rounded (GEMM2 consumes without further conversion)
    float* dst = base + (size_t)w * HIDDEN;
#pragma unroll
    for (int u = 0; u < 16; u++)
        dst[u * 32 + lane] = __uint_as_float(cvt_tf32(r[u]));
}

// ---------------------------------------------------------------------------
// kernel_launch: 4 chunks on forked streams, with G1_k+1 chained after G1_k
// so GEMMs run back-to-back and each chunk's mobius/G2 overlaps the next
// chunk's G1 in the freed SMs.
// ---------------------------------------------------------------------------
extern "C" void kernel_launch(void* const* d_in, const int* in_sizes, int n_in,
                              void* d_out, int out_size)
{
    const float* nf     = (const float*)d_in[0];
    const float* curv   = (const float*)d_in[1];
    const float* to_w   = (const float*)d_in[2];
    const float* to_b   = (const float*)d_in[3];
    const float* from_w = (const float*)d_in[4];
    const float* from_b = (const float*)d_in[5];
    const float* mw     = (const float*)d_in[6];
    float* out = (float*)d_out;

    float *scratch, *w1, *w2;
    cudaGetSymbolAddress((void**)&scratch, g_scratch);
    cudaGetSymbolAddress((void**)&w1,      g_w1);
    cudaGetSymbolAddress((void**)&w2,      g_w2);

    cudaFuncSetAttribute(gemm_cp<true>,  cudaFuncAttributeMaxDynamicSharedMemorySize,
                         DYN_SMEM_BYTES);
    cudaFuncSetAttribute(gemm_cp<false>, cudaFuncAttributeMaxDynamicSharedMemorySize,
                         DYN_SMEM_BYTES);

    // Prepasses on the origin (capture) stream.
    round_kernel<<<128, 256>>>((const float4*)to_w,   (float4*)w1, HIDDEN * HIDDEN / 4);
    round_kernel<<<128, 256>>>((const float4*)from_w, (float4*)w2, HIDDEN * HIDDEN / 4);
    yy_kernel<<<NUM_NODES * NUM_NODES, 32>>>(mw);

    // Fork NCHUNKS streams off the origin stream.
    cudaStream_t s[NCHUNKS];
    cudaEvent_t  eFork, eJoin[NCHUNKS], eG1[NCHUNKS];
    cudaEventCreateWithFlags(&eFork, cudaEventDisableTiming);
    cudaEventRecord(eFork, 0);
    for (int k = 0; k < NCHUNKS; k++) {
        cudaStreamCreateWithFlags(&s[k], cudaStreamNonBlocking);
        cudaEventCreateWithFlags(&eJoin[k], cudaEventDisableTiming);
        cudaEventCreateWithFlags(&eG1[k],   cudaEventDisableTiming);
        cudaStreamWaitEvent(s[k], eFork, 0);
    }

    dim3 gg(HIDDEN / BN, ROWS_PER_CHUNK / BM);   // (4, 144)

    for (int k = 0; k < NCHUNKS; k++) {
        const size_t rowOff = (size_t)k * ROWS_PER_CHUNK;
        const float* aPtr = nf      + rowOff * HIDDEN;
        float*       sPtr = scratch + rowOff * HIDDEN;
        float*       oPtr = out     + rowOff * HIDDEN;

        // Stagger: chunk k's G1 starts only after chunk k-1's G1 completes.
        if (k > 0) cudaStreamWaitEvent(s[k], eG1[k - 1], 0);

        gemm_cp<true><<<gg, 128, DYN_SMEM_BYTES, s[k]>>>(aPtr, w1, to_b, sPtr);
        cudaEventRecord(eG1[k], s[k]);

        mobius_kernel<<<BATCH_PER_CHUNK, 288, 0, s[k]>>>(sPtr, mw, curv);
        gemm_cp<false><<<gg, 128, DYN_SMEM_BYTES, s[k]>>>(sPtr, w2, from_b, oPtr);

        cudaEventRecord(eJoin[k], s[k]);
    }

    for (int k = 0; k < NCHUNKS; k++)
        cudaStreamWaitEvent(0, eJoin[k], 0);

    for (int k = 0; k < NCHUNKS; k++) {
        cudaStreamDestroy(s[k]);
        cudaEventDestroy(eJoin[k]);
        cudaEventDestroy(eG1[k]);
    }
    cudaEventDestroy(eFork);
}

// round 14
// speedup vs baseline: 1.1794x; 1.0228x over previous
#include <cuda_runtime.h>
#include <cuda_bf16.h>
#include <math.h>
#include <cstdint>

#define NUM_NODES 9
#define HIDDEN    512
#define BATCH     8192
#define M_ROWS    (BATCH * NUM_NODES)   // 73728
#define EPS       1e-8f

#define NCHUNKS         4
#define BATCH_PER_CHUNK (BATCH / NCHUNKS)              // 2048
#define ROWS_PER_CHUNK  (BATCH_PER_CHUNK * NUM_NODES)  // 18432 = 144 * 128

// Scratch buffers (device globals; no dynamic alloc allowed).
__device__ float g_scratch[(size_t)M_ROWS * HIDDEN];   // x_proj -> h -> mobius out (tf32-rounded)
__device__ float g_w1[HIDDEN * HIDDEN];                // tf32-rounded to_w
__device__ float g_w2[HIDDEN * HIDDEN];                // tf32-rounded from_w
__device__ float g_yy[NUM_NODES * NUM_NODES];          // ||mw[i][j]||^2

__device__ __forceinline__ uint32_t smem_u32(const void* p) {
    uint32_t a;
    asm("{ .reg .u64 t; cvta.to.shared.u64 t, %1; cvt.u32.u64 %0, t; }" : "=r"(a) : "l"(p));
    return a;
}
__device__ __forceinline__ uint32_t cvt_tf32(float f) {
    uint32_t u;
    asm("cvt.rna.tf32.f32 %0, %1;" : "=r"(u) : "f"(f));
    return u;
}

#define CP_ASYNC16(saddr, gptr) \
    asm volatile("cp.async.cg.shared.global [%0], [%1], 16;" :: "r"(saddr), "l"(gptr) : "memory")
#define CP_COMMIT() asm volatile("cp.async.commit_group;" ::: "memory")
#define CP_WAIT(n)  asm volatile("cp.async.wait_group %0;" :: "n"(n) : "memory")

__device__ __forceinline__ void mma_tf32(float* d, const uint32_t* a, const uint32_t* b) {
    asm volatile(
        "mma.sync.aligned.m16n8k8.row.col.f32.tf32.tf32.f32 "
        "{%0,%1,%2,%3}, {%4,%5,%6,%7}, {%8,%9}, {%0,%1,%2,%3};"
        : "+f"(d[0]), "+f"(d[1]), "+f"(d[2]), "+f"(d[3])
        : "r"(a[0]), "r"(a[1]), "r"(a[2]), "r"(a[3]), "r"(b[0]), "r"(b[1]));
}

// ---------------------------------------------------------------------------
// tf32 round prepass (weights only — tiny)
// ---------------------------------------------------------------------------
__global__ void round_kernel(const float4* __restrict__ in, float4* __restrict__ out, int n4) {
    int i = blockIdx.x * blockDim.x + threadIdx.x;
    int stride = gridDim.x * blockDim.x;
    for (; i < n4; i += stride) {
        float4 v = in[i];
        uint4 u = make_uint4(cvt_tf32(v.x), cvt_tf32(v.y), cvt_tf32(v.z), cvt_tf32(v.w));
        out[i] = *(float4*)&u;
    }
}

// ---------------------------------------------------------------------------
// TF32 mma.sync GEMM, cp.async 2-stage pipeline.
// CTA 128x128, 128 threads, 4 warps (2M x 2N), warp tile 64x64.
// __launch_bounds__(128,3): 3 CTAs/SM (221 KB smem, regs <= 170) ->
// 12 warps/SM = 3 warps/SMSP for latency hiding. Fragments single-buffered
// (the fully-unrolled s-loop lets ptxas pipeline loads into free regs).
// ---------------------------------------------------------------------------
#define BM 128
#define BN 128
#define LDS_PITCH 36
#define KCHUNKS (HIDDEN / 32)            // 16
#define T_BUF (128 * LDS_PITCH)          // 4608 floats / operand / stage
#define STAGES 2
#define DYN_SMEM_BYTES (STAGES * 2 * T_BUF * 4)   // 73728 B

template<bool CVT_A>
__global__ __launch_bounds__(128, 3)
void gemm_cp(const float* __restrict__ A,
             const float* __restrict__ W,
             const float* __restrict__ bias,
             float* __restrict__ C)
{
    extern __shared__ __align__(16) float smem[];
    const uint32_t smem_base = smem_u32(smem);
    const uint32_t sA0 = smem_base;
    const uint32_t sB0 = smem_base + STAGES * T_BUF * 4;

    const int tid  = threadIdx.x;
    const int bm   = blockIdx.y * BM;
    const int bn   = blockIdx.x * BN;
    const int lane = tid & 31;
    const int wid  = tid >> 5;
    const int m0w  = (wid & 1) * 64;
    const int n0w  = (wid >> 1) * 64;
    const int g    = lane >> 2;
    const int t    = lane & 3;

    const int r = tid >> 3;               // 0..15 (rows r + 16*i)
    const int q = tid & 7;                // 0..7

    const float* aG = A + (size_t)(bm + r) * HIDDEN + q * 4;
    const float* bG = W + (size_t)(bn + r) * HIDDEN + q * 4;
    const uint32_t aS = sA0 + (uint32_t)(r * LDS_PITCH + q * 4) * 4;
    const uint32_t bS = sB0 + (uint32_t)(r * LDS_PITCH + q * 4) * 4;

    float acc[4][8][4];
#pragma unroll
    for (int mi = 0; mi < 4; mi++)
#pragma unroll
        for (int ni = 0; ni < 8; ni++)
#pragma unroll
            for (int e = 0; e < 4; e++) acc[mi][ni][e] = 0.f;

#define ISSUE_STAGE(ck, st) do { \
    const float* _ag = aG + (ck) * 32; \
    const float* _bg = bG + (ck) * 32; \
    uint32_t _as = aS + (uint32_t)(st) * (T_BUF * 4); \
    uint32_t _bs = bS + (uint32_t)(st) * (T_BUF * 4); \
    _Pragma("unroll") \
    for (int _i = 0; _i < 8; _i++) \
        CP_ASYNC16(_as + _i * 16 * LDS_PITCH * 4, _ag + (size_t)_i * 16 * HIDDEN); \
    _Pragma("unroll") \
    for (int _i = 0; _i < 8; _i++) \
        CP_ASYNC16(_bs + _i * 16 * LDS_PITCH * 4, _bg + (size_t)_i * 16 * HIDDEN); \
    CP_COMMIT(); \
} while (0)

    ISSUE_STAGE(0, 0);

#define LDA(v) (CVT_A ? cvt_tf32(v) : __float_as_uint(v))

    for (int ck = 0; ck < KCHUNKS; ck++) {
        const int st = ck & 1;
        CP_WAIT(0);
        __syncthreads();
        if (ck + 1 < KCHUNKS)
            ISSUE_STAGE(ck + 1, st ^ 1);

        const float* cA = smem + st * T_BUF;
        const float* cB = smem + STAGES * T_BUF + st * T_BUF;

#pragma unroll
        for (int s = 0; s < 4; s++) {
            const int kc = s * 8;
            uint32_t af[4][4];
#pragma unroll
            for (int mi = 0; mi < 4; mi++) {
                const float* ap = cA + (m0w + mi * 16 + g) * LDS_PITCH + kc + t;
                af[mi][0] = LDA(ap[0]);
                af[mi][1] = LDA(ap[8 * LDS_PITCH]);
                af[mi][2] = LDA(ap[4]);
                af[mi][3] = LDA(ap[8 * LDS_PITCH + 4]);
            }
            uint32_t bf[8][2];
#pragma unroll
            for (int ni = 0; ni < 8; ni++) {
                const float* bp = cB + (n0w + ni * 8 + g) * LDS_PITCH + kc + t;
                bf[ni][0] = __float_as_uint(bp[0]);
                bf[ni][1] = __float_as_uint(bp[4]);
            }
#pragma unroll
            for (int mi = 0; mi < 4; mi++)
#pragma unroll
                for (int ni = 0; ni < 8; ni++)
                    mma_tf32(acc[mi][ni], af[mi], bf[ni]);
        }
    }
#undef LDA

    // epilogue: bias + store
#pragma unroll
    for (int ni = 0; ni < 8; ni++) {
        const int n = bn + n0w + ni * 8 + t * 2;
        const float b0 = __ldg(&bias[n]);
        const float b1 = __ldg(&bias[n + 1]);
#pragma unroll
        for (int mi = 0; mi < 4; mi++) {
            const int m = bm + m0w + mi * 16 + g;
            float2 v0 = make_float2(acc[mi][ni][0] + b0, acc[mi][ni][1] + b1);
            float2 v1 = make_float2(acc[mi][ni][2] + b0, acc[mi][ni][3] + b1);
            *(float2*)&C[(size_t)m * HIDDEN + n]       = v0;
            *(float2*)&C[(size_t)(m + 8) * HIDDEN + n] = v1;
        }
    }
}

// ---------------------------------------------------------------------------
// warp reduction + yy precompute
// ---------------------------------------------------------------------------
__device__ __forceinline__ float warpSum(float v) {
    v += __shfl_xor_sync(0xffffffffu, v, 16);
    v += __shfl_xor_sync(0xffffffffu, v, 8);
    v += __shfl_xor_sync(0xffffffffu, v, 4);
    v += __shfl_xor_sync(0xffffffffu, v, 2);
    v += __shfl_xor_sync(0xffffffffu, v, 1);
    return v;
}

__global__ void yy_kernel(const float* __restrict__ mw) {
    const int idx  = blockIdx.x;
    const int lane = threadIdx.x;
    const float* p = mw + (size_t)idx * HIDDEN;
    float s = 0.f;
#pragma unroll
    for (int u = 0; u < 16; u++) { float v = p[u * 32 + lane]; s += v * v; }
    s = warpSum(s);
    if (lane == 0) g_yy[idx] = s;
}

// ---------------------------------------------------------------------------
// Mobius aggregation (NB=1 winner, verbatim): one block per batch element,
// 9 warps (one per node). Writes tf32-rounded output.
// ---------------------------------------------------------------------------
__device__ const int d_ncnt[9]   = {3, 3, 2, 3, 3, 2, 3, 3, 8};
__device__ const int d_nbr[9][8] = {
    {4, 7, 8, 0, 0, 0, 0, 0},
    {0, 6, 8, 0, 0, 0, 0, 0},
    {5, 8, 0, 0, 0, 0, 0, 0},
    {1, 4, 8, 0, 0, 0, 0, 0},
    {6, 3, 8, 0, 0, 0, 0, 0},
    {2, 8, 0, 0, 0, 0, 0, 0},
    {7, 1, 8, 0, 0, 0, 0, 0},
    {3, 0, 8, 0, 0, 0, 0, 0},
    {0, 1, 2, 3, 4, 5, 6, 7}
};

__global__ __launch_bounds__(288)
void mobius_kernel(float* __restrict__ buf,
                   const float* __restrict__ mw,
                   const float* __restrict__ curv)
{
    __shared__ __align__(16) float sh[NUM_NODES * HIDDEN];
    __shared__ float sh_xx[NUM_NODES];

    const int b   = blockIdx.x;
    const int tid = threadIdx.x;
    const float c = fabsf(curv[0]);
    float* base = buf + (size_t)b * NUM_NODES * HIDDEN;

    for (int idx = tid; idx < NUM_NODES * HIDDEN / 4; idx += 288)
        ((float4*)sh)[idx] = ((const float4*)base)[idx];
    __syncthreads();

    const int w    = tid >> 5;
    const int lane = tid & 31;

    float r[16];
    float n2 = 0.f;
#pragma unroll
    for (int u = 0; u < 16; u++) {
        r[u] = sh[w * HIDDEN + u * 32 + lane];
        n2 += r[u] * r[u];
    }
    n2 = warpSum(n2);
    float norm  = sqrtf(n2);
    float scale = tanhf(norm) / (norm + EPS);
    float rr = scale * scale * n2;
#pragma unroll
    for (int u = 0; u < 16; u++) {
        r[u] *= scale;
        sh[w * HIDDEN + u * 32 + lane] = r[u];
    }
    if (lane == 0) sh_xx[w] = rr;
    __syncthreads();

    const int cnt = d_ncnt[w];
    for (int q = 0; q < cnt; q++) {
        const int j = d_nbr[w][q];
        const float* mwp = mw + ((size_t)w * NUM_NODES + j) * HIDDEN;
        const float yy = __ldg(&g_yy[w * NUM_NODES + j]);

        float hj[16], mv[16];
        float xy = 0.f;
#pragma unroll
        for (int u = 0; u < 16; u++) {
            hj[u] = sh[j * HIDDEN + u * 32 + lane];
            mv[u] = __ldg(&mwp[u * 32 + lane]);
            xy += hj[u] * mv[u];
        }
        xy = warpSum(xy);
        const float xxj = sh_xx[j];

        const float ca  = 1.f + 2.f * c * xy + c * yy;
        const float cb  = 1.f - c * xxj;
        const float inv = 1.f / (1.f + 2.f * c * xy + c * c * xxj * yy + EPS);
        const float tt  = inv * inv * (ca * ca * xxj + 2.f * ca * cb * xy + cb * cb * yy);

        float t[16];
        float rt = 0.f;
#pragma unroll
        for (int u = 0; u < 16; u++) {
            t[u] = (ca * hj[u] + cb * mv[u]) * inv;
            rt += r[u] * t[u];
        }
        rt = warpSum(rt);

        const float ca2  = 1.f + 2.f * c * rt + c * tt;
        const float cb2  = 1.f - c * rr;
        const float inv2 = 1.f / (1.f + 2.f * c * rt + c * c * rr * tt + EPS);
#pragma unroll
        for (int u = 0; u < 16; u++)
            r[u] = (ca2 * r[u] + cb2 * t[u]) * inv2;
        rr = inv2 * inv2 * (ca2 * ca2 * rr + 2.f * ca2 * cb2 * rt + cb2 * cb2 * tt);
    }

    // store tf32-rounded (GEMM2 consumes without further conversion)
    float* dst = base + (size_t)w * HIDDEN;
#pragma unroll
    for (int u = 0; u < 16; u++)
        dst[u * 32 + lane] = __uint_as_float(cvt_tf32(r[u]));
}

// ---------------------------------------------------------------------------
// kernel_launch: 4 chunks on forked streams, G1 chain-staggered (R13).
// ---------------------------------------------------------------------------
extern "C" void kernel_launch(void* const* d_in, const int* in_sizes, int n_in,
                              void* d_out, int out_size)
{
    const float* nf     = (const float*)d_in[0];
    const float* curv   = (const float*)d_in[1];
    const float* to_w   = (const float*)d_in[2];
    const float* to_b   = (const float*)d_in[3];
    const float* from_w = (const float*)d_in[4];
    const float* from_b = (const float*)d_in[5];
    const float* mw     = (const float*)d_in[6];
    float* out = (float*)d_out;

    float *scratch, *w1, *w2;
    cudaGetSymbolAddress((void**)&scratch, g_scratch);
    cudaGetSymbolAddress((void**)&w1,      g_w1);
    cudaGetSymbolAddress((void**)&w2,      g_w2);

    cudaFuncSetAttribute(gemm_cp<true>,  cudaFuncAttributeMaxDynamicSharedMemorySize,
                         DYN_SMEM_BYTES);
    cudaFuncSetAttribute(gemm_cp<false>, cudaFuncAttributeMaxDynamicSharedMemorySize,
                         DYN_SMEM_BYTES);

    // Prepasses on the origin (capture) stream.
    round_kernel<<<128, 256>>>((const float4*)to_w,   (float4*)w1, HIDDEN * HIDDEN / 4);
    round_kernel<<<128, 256>>>((const float4*)from_w, (float4*)w2, HIDDEN * HIDDEN / 4);
    yy_kernel<<<NUM_NODES * NUM_NODES, 32>>>(mw);

    // Fork NCHUNKS streams off the origin stream.
    cudaStream_t s[NCHUNKS];
    cudaEvent_t  eFork, eJoin[NCHUNKS], eG1[NCHUNKS];
    cudaEventCreateWithFlags(&eFork, cudaEventDisableTiming);
    cudaEventRecord(eFork, 0);
    for (int k = 0; k < NCHUNKS; k++) {
        cudaStreamCreateWithFlags(&s[k], cudaStreamNonBlocking);
        cudaEventCreateWithFlags(&eJoin[k], cudaEventDisableTiming);
        cudaEventCreateWithFlags(&eG1[k],   cudaEventDisableTiming);
        cudaStreamWaitEvent(s[k], eFork, 0);
    }

    dim3 gg(HIDDEN / BN, ROWS_PER_CHUNK / BM);   // (4, 144)

    for (int k = 0; k < NCHUNKS; k++) {
        const size_t rowOff = (size_t)k * ROWS_PER_CHUNK;
        const float* aPtr = nf      + rowOff * HIDDEN;
        float*       sPtr = scratch + rowOff * HIDDEN;
        float*       oPtr = out     + rowOff * HIDDEN;

        if (k > 0) cudaStreamWaitEvent(s[k], eG1[k - 1], 0);

        gemm_cp<true><<<gg, 128, DYN_SMEM_BYTES, s[k]>>>(aPtr, w1, to_b, sPtr);
        cudaEventRecord(eG1[k], s[k]);

        mobius_kernel<<<BATCH_PER_CHUNK, 288, 0, s[k]>>>(sPtr, mw, curv);
        gemm_cp<false><<<gg, 128, DYN_SMEM_BYTES, s[k]>>>(sPtr, w2, from_b, oPtr);

        cudaEventRecord(eJoin[k], s[k]);
    }

    for (int k = 0; k < NCHUNKS; k++)
        cudaStreamWaitEvent(0, eJoin[k], 0);

    for (int k = 0; k < NCHUNKS; k++) {
        cudaStreamDestroy(s[k]);
        cudaEventDestroy(eJoin[k]);
        cudaEventDestroy(eG1[k]);
    }
    cudaEventDestroy(eFork);
}

// round 15
// speedup vs baseline: 1.1806x; 1.0011x over previous
#include <cuda_runtime.h>
#include <cuda_bf16.h>
#include <math.h>
#include <cstdint>

#define NUM_NODES 9
#define HIDDEN    512
#define BATCH     8192
#define M_ROWS    (BATCH * NUM_NODES)   // 73728
#define EPS       1e-8f

#define NCHUNKS         4
#define BATCH_PER_CHUNK (BATCH / NCHUNKS)              // 2048
#define ROWS_PER_CHUNK  (BATCH_PER_CHUNK * NUM_NODES)  // 18432 = 144 * 128

// Scratch buffers (device globals; no dynamic alloc allowed).
__device__ float g_scratch[(size_t)M_ROWS * HIDDEN];   // x_proj -> h -> mobius out (tf32+perm)
__device__ float g_w1[HIDDEN * HIDDEN];                // tf32-rounded to_w
__device__ float g_w2[HIDDEN * HIDDEN];                // tf32-rounded + k-permuted from_w
__device__ float g_yy[NUM_NODES * NUM_NODES];          // ||mw[i][j]||^2

__device__ __forceinline__ uint32_t smem_u32(const void* p) {
    uint32_t a;
    asm("{ .reg .u64 t; cvta.to.shared.u64 t, %1; cvt.u32.u64 %0, t; }" : "=r"(a) : "l"(p));
    return a;
}
__device__ __forceinline__ uint32_t cvt_tf32(float f) {
    uint32_t u;
    asm("cvt.rna.tf32.f32 %0, %1;" : "=r"(u) : "f"(f));
    return u;
}

#define CP_ASYNC16(saddr, gptr) \
    asm volatile("cp.async.cg.shared.global [%0], [%1], 16;" :: "r"(saddr), "l"(gptr) : "memory")
#define CP_COMMIT() asm volatile("cp.async.commit_group;" ::: "memory")
#define CP_WAIT(n)  asm volatile("cp.async.wait_group %0;" :: "n"(n) : "memory")

__device__ __forceinline__ void mma_tf32(float* d, const uint32_t* a, const uint32_t* b) {
    asm volatile(
        "mma.sync.aligned.m16n8k8.row.col.f32.tf32.tf32.f32 "
        "{%0,%1,%2,%3}, {%4,%5,%6,%7}, {%8,%9}, {%0,%1,%2,%3};"
        : "+f"(d[0]), "+f"(d[1]), "+f"(d[2]), "+f"(d[3])
        : "r"(a[0]), "r"(a[1]), "r"(a[2]), "r"(a[3]), "r"(b[0]), "r"(b[1]));
}

// k-pair permutation within each octet: order [0,4,1,5,2,6,3,7]
__device__ __forceinline__ int kperm(int k7) {
    return (k7 < 4) ? 2 * k7 : 2 * (k7 - 4) + 1;
}

// ---------------------------------------------------------------------------
// Weight prepasses (tiny)
// ---------------------------------------------------------------------------
__global__ void round_kernel(const float4* __restrict__ in, float4* __restrict__ out, int n4) {
    int i = blockIdx.x * blockDim.x + threadIdx.x;
    int stride = gridDim.x * blockDim.x;
    for (; i < n4; i += stride) {
        float4 v = in[i];
        uint4 u = make_uint4(cvt_tf32(v.x), cvt_tf32(v.y), cvt_tf32(v.z), cvt_tf32(v.w));
        out[i] = *(float4*)&u;
    }
}
// round + k-permute (for the GEMM2 weight)
__global__ void round_perm_kernel(const float* __restrict__ in, float* __restrict__ out, int n) {
    int i = blockIdx.x * blockDim.x + threadIdx.x;
    int stride = gridDim.x * blockDim.x;
    for (; i < n; i += stride) {
        int pos = kperm(i & 7);
        out[(i & ~7) | pos] = __uint_as_float(cvt_tf32(in[i]));
    }
}

// ---------------------------------------------------------------------------
// TF32 mma.sync GEMM, cp.async 2-stage pipeline, __launch_bounds__(128,3).
// CTA 128x128, 128 threads, 4 warps (2M x 2N), warp tile 64x64.
// PERM=false: R14 path (pitch 36, scalar fragment LDS, optional in-LDS cvt).
// PERM=true:  operands pre-permuted (k-pairs adjacent) -> LDS.64 fragments,
//             pitch 32 with 32B XOR swizzle (chunk ^= (row&3)<<1): verified
//             conflict-free (row g spans banks 8(s^g)..+7) and per-thread-
//             constant for cp.async staging.
// ---------------------------------------------------------------------------
#define BM 128
#define BN 128
#define KCHUNKS (HIDDEN / 32)            // 16
#define STAGES 2

template<bool CVT_A, bool PERM>
__global__ __launch_bounds__(128, 3)
void gemm_cp(const float* __restrict__ A,
             const float* __restrict__ W,
             const float* __restrict__ bias,
             float* __restrict__ C)
{
    constexpr int PITCHF = PERM ? 32 : 36;        // floats per staged row
    constexpr int TB     = 128 * PITCHF;          // floats per operand per stage

    extern __shared__ __align__(16) float smem[];
    const uint32_t smem_base = smem_u32(smem);
    const uint32_t sA0 = smem_base;
    const uint32_t sB0 = smem_base + STAGES * TB * 4;

    const int tid  = threadIdx.x;
    const int bm   = blockIdx.y * BM;
    const int bn   = blockIdx.x * BN;
    const int lane = tid & 31;
    const int wid  = tid >> 5;
    const int m0w  = (wid & 1) * 64;
    const int n0w  = (wid >> 1) * 64;
    const int g    = lane >> 2;
    const int t    = lane & 3;

    const int r = tid >> 3;               // 0..15 (rows r + 16*i)
    const int q = tid & 7;                // 0..7

    const float* aG = A + (size_t)(bm + r) * HIDDEN + q * 4;
    const float* bG = W + (size_t)(bn + r) * HIDDEN + q * 4;

    uint32_t stOff;
    if (PERM) stOff = (uint32_t)(r * 128 + ((q ^ ((r & 3) << 1)) << 4));
    else      stOff = (uint32_t)(r * PITCHF + q * 4) * 4;
    const uint32_t aS = sA0 + stOff;
    const uint32_t bS = sB0 + stOff;

    float acc[4][8][4];
#pragma unroll
    for (int mi = 0; mi < 4; mi++)
#pragma unroll
        for (int ni = 0; ni < 8; ni++)
#pragma unroll
            for (int e = 0; e < 4; e++) acc[mi][ni][e] = 0.f;

#define ISSUE_STAGE(ck, st) do { \
    const float* _ag = aG + (ck) * 32; \
    const float* _bg = bG + (ck) * 32; \
    uint32_t _as = aS + (uint32_t)(st) * (TB * 4); \
    uint32_t _bs = bS + (uint32_t)(st) * (TB * 4); \
    _Pragma("unroll") \
    for (int _i = 0; _i < 8; _i++) \
        CP_ASYNC16(_as + _i * 16 * PITCHF * 4, _ag + (size_t)_i * 16 * HIDDEN); \
    _Pragma("unroll") \
    for (int _i = 0; _i < 8; _i++) \
        CP_ASYNC16(_bs + _i * 16 * PITCHF * 4, _bg + (size_t)_i * 16 * HIDDEN); \
    CP_COMMIT(); \
} while (0)

    ISSUE_STAGE(0, 0);

#define LDA(v) (CVT_A ? cvt_tf32(v) : __float_as_uint(v))

    for (int ck = 0; ck < KCHUNKS; ck++) {
        const int st = ck & 1;
        CP_WAIT(0);
        __syncthreads();
        if (ck + 1 < KCHUNKS)
            ISSUE_STAGE(ck + 1, st ^ 1);

        const float* cA = smem + st * TB;
        const float* cB = smem + STAGES * TB + st * TB;

#pragma unroll
        for (int s = 0; s < 4; s++) {
            uint32_t af[4][4], bf[8][2];
            if (PERM) {
                // LDS.64 fragments: pair (k=t, k=t+4) adjacent; swizzled chunk.
                const uint32_t c0 =
                    ((uint32_t)(((2 * s + (t >> 1)) ^ ((g & 3) << 1)) << 4)) + ((t & 1) << 3);
                const char* cAb = (const char*)cA;
                const char* cBb = (const char*)cB;
#pragma unroll
                for (int mi = 0; mi < 4; mi++) {
                    const char* p0 = cAb + (m0w + mi * 16 + g) * 128 + c0;
                    uint2 lo = *(const uint2*)p0;
                    uint2 hi = *(const uint2*)(p0 + 8 * 128);
                    af[mi][0] = lo.x; af[mi][2] = lo.y;
                    af[mi][1] = hi.x; af[mi][3] = hi.y;
                }
#pragma unroll
                for (int ni = 0; ni < 8; ni++) {
                    const char* pb = cBb + (n0w + ni * 8 + g) * 128 + c0;
                    uint2 bb = *(const uint2*)pb;
                    bf[ni][0] = bb.x; bf[ni][1] = bb.y;
                }
            } else {
                const int kc = s * 8;
#pragma unroll
                for (int mi = 0; mi < 4; mi++) {
                    const float* ap = cA + (m0w + mi * 16 + g) * PITCHF + kc + t;
                    af[mi][0] = LDA(ap[0]);
                    af[mi][1] = LDA(ap[8 * PITCHF]);
                    af[mi][2] = LDA(ap[4]);
                    af[mi][3] = LDA(ap[8 * PITCHF + 4]);
                }
#pragma unroll
                for (int ni = 0; ni < 8; ni++) {
                    const float* bp = cB + (n0w + ni * 8 + g) * PITCHF + kc + t;
                    bf[ni][0] = __float_as_uint(bp[0]);
                    bf[ni][1] = __float_as_uint(bp[4]);
                }
            }
#pragma unroll
            for (int mi = 0; mi < 4; mi++)
#pragma unroll
                for (int ni = 0; ni < 8; ni++)
                    mma_tf32(acc[mi][ni], af[mi], bf[ni]);
        }
    }
#undef LDA

    // epilogue: bias + store (normal layout)
#pragma unroll
    for (int ni = 0; ni < 8; ni++) {
        const int n = bn + n0w + ni * 8 + t * 2;
        const float b0 = __ldg(&bias[n]);
        const float b1 = __ldg(&bias[n + 1]);
#pragma unroll
        for (int mi = 0; mi < 4; mi++) {
            const int m = bm + m0w + mi * 16 + g;
            float2 v0 = make_float2(acc[mi][ni][0] + b0, acc[mi][ni][1] + b1);
            float2 v1 = make_float2(acc[mi][ni][2] + b0, acc[mi][ni][3] + b1);
            *(float2*)&C[(size_t)m * HIDDEN + n]       = v0;
            *(float2*)&C[(size_t)(m + 8) * HIDDEN + n] = v1;
        }
    }
}

#define DYN_SMEM_G1 (STAGES * 2 * (128 * 36) * 4)   // 73728 B
#define DYN_SMEM_G2 (STAGES * 2 * (128 * 32) * 4)   // 65536 B

// ---------------------------------------------------------------------------
// warp reduction + yy precompute
// ---------------------------------------------------------------------------
__device__ __forceinline__ float warpSum(float v) {
    v += __shfl_xor_sync(0xffffffffu, v, 16);
    v += __shfl_xor_sync(0xffffffffu, v, 8);
    v += __shfl_xor_sync(0xffffffffu, v, 4);
    v += __shfl_xor_sync(0xffffffffu, v, 2);
    v += __shfl_xor_sync(0xffffffffu, v, 1);
    return v;
}

__global__ void yy_kernel(const float* __restrict__ mw) {
    const int idx  = blockIdx.x;
    const int lane = threadIdx.x;
    const float* p = mw + (size_t)idx * HIDDEN;
    float s = 0.f;
#pragma unroll
    for (int u = 0; u < 16; u++) { float v = p[u * 32 + lane]; s += v * v; }
    s = warpSum(s);
    if (lane == 0) g_yy[idx] = s;
}

// ---------------------------------------------------------------------------
// Mobius aggregation (NB=1 winner): one block per batch element, 9 warps.
// Output stored tf32-rounded AND k-permuted (consumed only by GEMM2-PERM).
// ---------------------------------------------------------------------------
__device__ const int d_ncnt[9]   = {3, 3, 2, 3, 3, 2, 3, 3, 8};
__device__ const int d_nbr[9][8] = {
    {4, 7, 8, 0, 0, 0, 0, 0},
    {0, 6, 8, 0, 0, 0, 0, 0},
    {5, 8, 0, 0, 0, 0, 0, 0},
    {1, 4, 8, 0, 0, 0, 0, 0},
    {6, 3, 8, 0, 0, 0, 0, 0},
    {2, 8, 0, 0, 0, 0, 0, 0},
    {7, 1, 8, 0, 0, 0, 0, 0},
    {3, 0, 8, 0, 0, 0, 0, 0},
    {0, 1, 2, 3, 4, 5, 6, 7}
};

__global__ __launch_bounds__(288)
void mobius_kernel(float* __restrict__ buf,
                   const float* __restrict__ mw,
                   const float* __restrict__ curv)
{
    __shared__ __align__(16) float sh[NUM_NODES * HIDDEN];
    __shared__ float sh_xx[NUM_NODES];

    const int b   = blockIdx.x;
    const int tid = threadIdx.x;
    const float c = fabsf(curv[0]);
    float* base = buf + (size_t)b * NUM_NODES * HIDDEN;

    for (int idx = tid; idx < NUM_NODES * HIDDEN / 4; idx += 288)
        ((float4*)sh)[idx] = ((const float4*)base)[idx];
    __syncthreads();

    const int w    = tid >> 5;
    const int lane = tid & 31;

    float r[16];
    float n2 = 0.f;
#pragma unroll
    for (int u = 0; u < 16; u++) {
        r[u] = sh[w * HIDDEN + u * 32 + lane];
        n2 += r[u] * r[u];
    }
    n2 = warpSum(n2);
    float norm  = sqrtf(n2);
    float scale = tanhf(norm) / (norm + EPS);
    float rr = scale * scale * n2;
#pragma unroll
    for (int u = 0; u < 16; u++) {
        r[u] *= scale;
        sh[w * HIDDEN + u * 32 + lane] = r[u];
    }
    if (lane == 0) sh_xx[w] = rr;
    __syncthreads();

    const int cnt = d_ncnt[w];
    for (int q = 0; q < cnt; q++) {
        const int j = d_nbr[w][q];
        const float* mwp = mw + ((size_t)w * NUM_NODES + j) * HIDDEN;
        const float yy = __ldg(&g_yy[w * NUM_NODES + j]);

        float hj[16], mv[16];
        float xy = 0.f;
#pragma unroll
        for (int u = 0; u < 16; u++) {
            hj[u] = sh[j * HIDDEN + u * 32 + lane];
            mv[u] = __ldg(&mwp[u * 32 + lane]);
            xy += hj[u] * mv[u];
        }
        xy = warpSum(xy);
        const float xxj = sh_xx[j];

        const float ca  = 1.f + 2.f * c * xy + c * yy;
        const float cb  = 1.f - c * xxj;
        const float inv = 1.f / (1.f + 2.f * c * xy + c * c * xxj * yy + EPS);
        const float tt  = inv * inv * (ca * ca * xxj + 2.f * ca * cb * xy + cb * cb * yy);

        float t[16];
        float rt = 0.f;
#pragma unroll
        for (int u = 0; u < 16; u++) {
            t[u] = (ca * hj[u] + cb * mv[u]) * inv;
            rt += r[u] * t[u];
        }
        rt = warpSum(rt);

        const float ca2  = 1.f + 2.f * c * rt + c * tt;
        const float cb2  = 1.f - c * rr;
        const float inv2 = 1.f / (1.f + 2.f * c * rt + c * c * rr * tt + EPS);
#pragma unroll
        for (int u = 0; u < 16; u++)
            r[u] = (ca2 * r[u] + cb2 * t[u]) * inv2;
        rr = inv2 * inv2 * (ca2 * ca2 * rr + 2.f * ca2 * cb2 * rt + cb2 * cb2 * tt);
    }

    // store tf32-rounded, k-permuted (pairs (k,k+4) adjacent) for GEMM2
    const int pos   = kperm(lane & 7);
    const int plane = (lane & 24) | pos;
    float* dst = base + (size_t)w * HIDDEN;
#pragma unroll
    for (int u = 0; u < 16; u++)
        dst[u * 32 + plane] = __uint_as_float(cvt_tf32(r[u]));
}

// ---------------------------------------------------------------------------
// kernel_launch: 4 chunks on forked streams, G1 chain-staggered (R13).
// ---------------------------------------------------------------------------
extern "C" void kernel_launch(void* const* d_in, const int* in_sizes, int n_in,
                              void* d_out, int out_size)
{
    const float* nf     = (const float*)d_in[0];
    const float* curv   = (const float*)d_in[1];
    const float* to_w   = (const float*)d_in[2];
    const float* to_b   = (const float*)d_in[3];
    const float* from_w = (const float*)d_in[4];
    const float* from_b = (const float*)d_in[5];
    const float* mw     = (const float*)d_in[6];
    float* out = (float*)d_out;

    float *scratch, *w1, *w2;
    cudaGetSymbolAddress((void**)&scratch, g_scratch);
    cudaGetSymbolAddress((void**)&w1,      g_w1);
    cudaGetSymbolAddress((void**)&w2,      g_w2);

    cudaFuncSetAttribute((const void*)gemm_cp<true, false>,
                         cudaFuncAttributeMaxDynamicSharedMemorySize, DYN_SMEM_G1);
    cudaFuncSetAttribute((const void*)gemm_cp<false, true>,
                         cudaFuncAttributeMaxDynamicSharedMemorySize, DYN_SMEM_G2);

    // Prepasses on the origin (capture) stream.
    round_kernel<<<128, 256>>>((const float4*)to_w, (float4*)w1, HIDDEN * HIDDEN / 4);
    round_perm_kernel<<<256, 256>>>(from_w, w2, HIDDEN * HIDDEN);
    yy_kernel<<<NUM_NODES * NUM_NODES, 32>>>(mw);

    // Fork NCHUNKS streams off the origin stream.
    cudaStream_t s[NCHUNKS];
    cudaEvent_t  eFork, eJoin[NCHUNKS], eG1[NCHUNKS];
    cudaEventCreateWithFlags(&eFork, cudaEventDisableTiming);
    cudaEventRecord(eFork, 0);
    for (int k = 0; k < NCHUNKS; k++) {
        cudaStreamCreateWithFlags(&s[k], cudaStreamNonBlocking);
        cudaEventCreateWithFlags(&eJoin[k], cudaEventDisableTiming);
        cudaEventCreateWithFlags(&eG1[k],   cudaEventDisableTiming);
        cudaStreamWaitEvent(s[k], eFork, 0);
    }

    dim3 gg(HIDDEN / BN, ROWS_PER_CHUNK / BM);   // (4, 144)

    for (int k = 0; k < NCHUNKS; k++) {
        const size_t rowOff = (size_t)k * ROWS_PER_CHUNK;
        const float* aPtr = nf      + rowOff * HIDDEN;
        float*       sPtr = scratch + rowOff * HIDDEN;
        float*       oPtr = out     + rowOff * HIDDEN;

        if (k > 0) cudaStreamWaitEvent(s[k], eG1[k - 1], 0);

        gemm_cp<true, false><<<gg, 128, DYN_SMEM_G1, s[k]>>>(aPtr, w1, to_b, sPtr);
        cudaEventRecord(eG1[k], s[k]);

        mobius_kernel<<<BATCH_PER_CHUNK, 288, 0, s[k]>>>(sPtr, mw, curv);
        gemm_cp<false, true><<<gg, 128, DYN_SMEM_G2, s[k]>>>(sPtr, w2, from_b, oPtr);

        cudaEventRecord(eJoin[k], s[k]);
    }

    for (int k = 0; k < NCHUNKS; k++)
        cudaStreamWaitEvent(0, eJoin[k], 0);

    for (int k = 0; k < NCHUNKS; k++) {
        cudaStreamDestroy(s[k]);
        cudaEventDestroy(eJoin[k]);
        cudaEventDestroy(eG1[k]);
    }
    cudaEventDestroy(eFork);
}